// round 10
// baseline (speedup 1.0000x reference)
#include <cuda_runtime.h>
#include <cuda_bf16.h>
#include <math.h>
#include <stdint.h>

#define RTOK 2048
#define DIM  1024
#define NH   16
#define HDIM 64
#define MLPD 4096
#define NBH  32
#define SEQ  1024

// ------------------------- scratch (device globals) -------------------------
__device__ float g_x[RTOK * DIM];
__device__ __align__(128) __nv_bfloat16 g_a0[RTOK * DIM],  g_a1[RTOK * DIM];
__device__ __align__(128) __nv_bfloat16 g_h0[RTOK * MLPD], g_h1[RTOK * MLPD];
__device__ __align__(128) __nv_bfloat16 g_q0[RTOK * DIM],  g_q1[RTOK * DIM];
__device__ __align__(128) __nv_bfloat16 g_k0[RTOK * DIM],  g_k1[RTOK * DIM];
__device__ __align__(128) __nv_bfloat16 g_v0[RTOK * DIM],  g_v1[RTOK * DIM];
__device__ __align__(128) __nv_bfloat16 g_wq0[3*DIM*DIM], g_wq1[3*DIM*DIM];
__device__ __align__(128) __nv_bfloat16 g_wo0[DIM*DIM],   g_wo1[DIM*DIM];
__device__ __align__(128) __nv_bfloat16 g_w10[MLPD*DIM],  g_w11[MLPD*DIM];
__device__ __align__(128) __nv_bfloat16 g_w20[DIM*MLPD],  g_w21[DIM*MLPD];

// ------------------------- helpers -------------------------
__device__ __forceinline__ uint32_t smem_u32(const void* p) {
    uint32_t a;
    asm("{ .reg .u64 t; cvta.to.shared.u64 t, %1; cvt.u32.u64 %0, t; }" : "=r"(a) : "l"(p));
    return a;
}
__device__ __forceinline__ uint32_t sw128(uint32_t off) { return off ^ ((off >> 3) & 0x70); }

__device__ __forceinline__ size_t packed_off(int row, int col, int K) {
    int rb = row >> 7, kc = col >> 6;
    uint32_t off = ((uint32_t)(row & 127) << 7) | ((uint32_t)(col & 63) << 1);
    off = off ^ ((off >> 3) & 0x70);
    return ((size_t)(rb * (K >> 6) + kc) << 14) + off;
}

__device__ __forceinline__ void mbar_init(uint32_t a, uint32_t cnt) {
    asm volatile("mbarrier.init.shared.b64 [%0], %1;" :: "r"(a), "r"(cnt) : "memory");
}
__device__ __forceinline__ void mbar_expect_tx(uint32_t a, uint32_t bytes) {
    asm volatile("mbarrier.arrive.expect_tx.shared.b64 _, [%0], %1;" :: "r"(a), "r"(bytes) : "memory");
}
__device__ __forceinline__ void mbar_wait(uint32_t a, uint32_t parity) {
    asm volatile(
        "{\n\t.reg .pred P1;\n\t"
        "LAB_WAIT_%=:\n\t"
        "mbarrier.try_wait.parity.acquire.cta.shared::cta.b64 P1, [%0], %1, 0x989680;\n\t"
        "@P1 bra.uni LAB_DONE_%=;\n\t"
        "bra.uni LAB_WAIT_%=;\n\t"
        "LAB_DONE_%=:\n\t}"
        :: "r"(a), "r"(parity) : "memory");
}
__device__ __forceinline__ void bulk_g2s(uint32_t dst, const void* src, uint32_t bytes, uint32_t mbar) {
    asm volatile(
        "cp.async.bulk.shared::cta.global.mbarrier::complete_tx::bytes [%0], [%1], %2, [%3];"
        :: "r"(dst), "l"(src), "r"(bytes), "r"(mbar) : "memory");
}
__device__ __forceinline__ void ldsm4(uint32_t* r, uint32_t addr) {
    asm volatile("ldmatrix.sync.aligned.m8n8.x4.shared.b16 {%0,%1,%2,%3}, [%4];"
                 : "=r"(r[0]), "=r"(r[1]), "=r"(r[2]), "=r"(r[3]) : "r"(addr));
}
__device__ __forceinline__ void ldsm4t(uint32_t* r, uint32_t addr) {
    asm volatile("ldmatrix.sync.aligned.m8n8.x4.trans.shared.b16 {%0,%1,%2,%3}, [%4];"
                 : "=r"(r[0]), "=r"(r[1]), "=r"(r[2]), "=r"(r[3]) : "r"(addr));
}
__device__ __forceinline__ void mma16816(float* c, const uint32_t* a, const uint32_t* b) {
    asm volatile(
        "mma.sync.aligned.m16n8k16.row.col.f32.bf16.bf16.f32 "
        "{%0,%1,%2,%3}, {%4,%5,%6,%7}, {%8,%9}, {%0,%1,%2,%3};"
        : "+f"(c[0]), "+f"(c[1]), "+f"(c[2]), "+f"(c[3])
        : "r"(a[0]), "r"(a[1]), "r"(a[2]), "r"(a[3]), "r"(b[0]), "r"(b[1]));
}
__device__ __forceinline__ float ex2(float x) {
    float y; asm("ex2.approx.f32 %0, %1;" : "=f"(y) : "f"(x)); return y;
}
__device__ __forceinline__ uint32_t bpack_hi(float x, float y) {
    __nv_bfloat162 t(__float2bfloat16(x), __float2bfloat16(y));
    return *reinterpret_cast<uint32_t*>(&t);
}
__device__ __forceinline__ uint32_t bpack_lo(float x, float y) {
    __nv_bfloat16 hx = __float2bfloat16(x), hy = __float2bfloat16(y);
    __nv_bfloat162 t(__float2bfloat16(x - __bfloat162float(hx)),
                     __float2bfloat16(y - __bfloat162float(hy)));
    return *reinterpret_cast<uint32_t*>(&t);
}

#define TILE_BYTES  16384
#define STAGE_BYTES 65536
#define SM_TILES    1024
#define NSTAGE      3
#define SM_TOTAL    (SM_TILES + NSTAGE * STAGE_BYTES)

// ------------------------- bf16-split tensor GEMM 128x128 (R6 best config) ------------
__global__ __launch_bounds__(256, 1) void gemm_tc(
    const char* __restrict__ A0, const char* __restrict__ A1,
    const char* __restrict__ B0, const char* __restrict__ B1,
    const float* __restrict__ bias, const float* __restrict__ Res,
    float* __restrict__ Cf, char* __restrict__ C0, char* __restrict__ C1,
    char* __restrict__ K0o, char* __restrict__ K1o,
    char* __restrict__ V0o, char* __restrict__ V1o,
    int N, int K, int epi)
{
    extern __shared__ char smem[];
    uint32_t sb = smem_u32(smem);
    int tid = threadIdx.x, wid = tid >> 5, lane = tid & 31;
    int m0 = blockIdx.y * 128, n0 = blockIdx.x * 128;
    int warp_m = (wid >> 1) * 32, warp_n = (wid & 1) * 64;
    const int NC = K >> 6;

    if (tid == 0) { mbar_init(sb, 1); mbar_init(sb + 8, 1); mbar_init(sb + 16, 1); }
    __syncthreads();

    size_t abase = ((size_t)((m0 >> 7) * NC)) << 14;
    size_t bbase = ((size_t)((n0 >> 7) * NC)) << 14;

    auto load_chunk = [&](int c, int s) {
        uint32_t mb = sb + s * 8;
        uint32_t dst = sb + SM_TILES + s * STAGE_BYTES;
        size_t go = (size_t)c << 14;
        mbar_expect_tx(mb, STAGE_BYTES);
        bulk_g2s(dst,                 A0 + abase + go, TILE_BYTES, mb);
        bulk_g2s(dst + TILE_BYTES,    A1 + abase + go, TILE_BYTES, mb);
        bulk_g2s(dst + 2*TILE_BYTES,  B0 + bbase + go, TILE_BYTES, mb);
        bulk_g2s(dst + 3*TILE_BYTES,  B1 + bbase + go, TILE_BYTES, mb);
    };

    if (tid == 0) { load_chunk(0, 0); load_chunk(1, 1); }

    float acc[2][8][4];
#pragma unroll
    for (int i = 0; i < 2; i++)
#pragma unroll
        for (int j = 0; j < 8; j++)
#pragma unroll
            for (int q = 0; q < 4; q++) acc[i][j][q] = 0.f;

    int a_row = warp_m + (lane & 15);
    int a_ks  = (lane >> 4) << 4;
    int b_nr  = warp_n + ((lane >> 4) << 3) + (lane & 7);
    int b_ks  = ((lane >> 3) & 1) << 4;

    int stage = 0, phase = 0;
    for (int c = 0; c < NC; c++) {
        mbar_wait(sb + stage * 8, phase);
        if (tid == 0 && c + 2 < NC) {
            int s2 = stage + 2; if (s2 >= NSTAGE) s2 -= NSTAGE;
            load_chunk(c + 2, s2);
        }

        uint32_t base = sb + SM_TILES + stage * STAGE_BYTES;
#pragma unroll
        for (int ks = 0; ks < 4; ks++) {
            uint32_t aA[2][2][4];
#pragma unroll
            for (int mi = 0; mi < 2; mi++) {
                uint32_t off = sw128((uint32_t)(a_row + mi * 16) * 128 + ks * 32 + a_ks);
                ldsm4(aA[mi][0], base + off);
                ldsm4(aA[mi][1], base + TILE_BYTES + off);
            }
#pragma unroll
            for (int nj = 0; nj < 4; nj++) {
                uint32_t boff = sw128((uint32_t)(b_nr + nj * 16) * 128 + ks * 32 + b_ks);
                uint32_t b0[4], b1[4];
                ldsm4(b0, base + 2 * TILE_BYTES + boff);
                ldsm4(b1, base + 3 * TILE_BYTES + boff);
#pragma unroll
                for (int mi = 0; mi < 2; mi++)
#pragma unroll
                    for (int nf = 0; nf < 2; nf++)
                        mma16816(acc[mi][nj * 2 + nf], aA[mi][0], b0 + 2 * nf);
#pragma unroll
                for (int mi = 0; mi < 2; mi++)
#pragma unroll
                    for (int nf = 0; nf < 2; nf++)
                        mma16816(acc[mi][nj * 2 + nf], aA[mi][0], b1 + 2 * nf);
#pragma unroll
                for (int mi = 0; mi < 2; mi++)
#pragma unroll
                    for (int nf = 0; nf < 2; nf++)
                        mma16816(acc[mi][nj * 2 + nf], aA[mi][1], b0 + 2 * nf);
            }
        }
        __syncthreads();
        if (++stage == NSTAGE) { stage = 0; phase ^= 1; }
    }

    int mrow = m0 + warp_m + (lane >> 2);
    int ncol = n0 + warp_n + (lane & 3) * 2;
#pragma unroll
    for (int mi = 0; mi < 2; mi++) {
#pragma unroll
        for (int nj = 0; nj < 8; nj++) {
#pragma unroll
            for (int h = 0; h < 2; h++) {
                int m = mrow + mi * 16 + h * 8;
                int n = ncol + nj * 8;
                float v0 = acc[mi][nj][2 * h];
                float v1 = acc[mi][nj][2 * h + 1];
                if (epi == 0) {
                    *reinterpret_cast<float2*>(Cf + (size_t)m * N + n) = make_float2(v0, v1);
                } else if (epi == 1) {
                    size_t off = (size_t)m * N + n;
                    float2 r = *reinterpret_cast<const float2*>(Res + off);
                    *reinterpret_cast<float2*>(Cf + off) =
                        make_float2(v0 + bias[n] + r.x, v1 + bias[n + 1] + r.y);
                } else if (epi == 2) {
                    float t0 = v0 + bias[n],     t1 = v1 + bias[n + 1];
                    float g0 = 0.5f * t0 * (1.0f + erff(t0 * 0.70710678118654752f));
                    float g1 = 0.5f * t1 * (1.0f + erff(t1 * 0.70710678118654752f));
                    size_t po = packed_off(m, n, N);
                    *reinterpret_cast<uint32_t*>(C0 + po) = bpack_hi(g0, g1);
                    *reinterpret_cast<uint32_t*>(C1 + po) = bpack_lo(g0, g1);
                } else {
                    int sel = n >> 10;
                    int hh  = (n >> 6) & 15;
                    int d   = n & 63;
                    int bb  = m >> 10;
                    int qq  = m & 1023;
                    int blk = ((bb * 16 + hh) * 8) + (qq >> 7);
                    uint32_t off = (uint32_t)(qq & 127) * 128 + d * 2;
                    off ^= (off >> 3) & 0x70;
                    size_t po = ((size_t)blk << 14) + off;
                    char* D0 = (sel == 0) ? C0 : (sel == 1) ? K0o : V0o;
                    char* D1 = (sel == 0) ? C1 : (sel == 1) ? K1o : V1o;
                    *reinterpret_cast<uint32_t*>(D0 + po) = bpack_hi(v0, v1);
                    *reinterpret_cast<uint32_t*>(D1 + po) = bpack_lo(v0, v1);
                }
            }
        }
    }
}

// ------------------------- flash attention v2: 256 q-rows/CTA, single wave ------------
// grid (4, 32). Q resident in smem (64KB, 2 halves), KV 2-stage (128KB).
#define FL_SMQ   1024
#define FL_SMKV  (1024 + 65536)
#define FL_STAGE 65536
#define FL_TOTAL (1024 + 65536 + 2 * 65536)

__global__ __launch_bounds__(256, 1) void flash_kernel(
    const char* __restrict__ Q0, const char* __restrict__ Q1,
    const char* __restrict__ K0, const char* __restrict__ K1,
    const char* __restrict__ V0, const char* __restrict__ V1,
    char* __restrict__ O0, char* __restrict__ O1)
{
    extern __shared__ char smem[];
    uint32_t sb = smem_u32(smem);
    int tid = threadIdx.x, wid = tid >> 5, lane = tid & 31;
    int qb2 = blockIdx.x, bh = blockIdx.y;
    const float SCALE_LOG2E = 0.03125f * 1.44269504088896341f;

    if (tid == 0) { mbar_init(sb, 1); mbar_init(sb + 8, 1); mbar_init(sb + 16, 1); }
    __syncthreads();

    auto load_chunk = [&](int j, int s) {
        uint32_t mb = sb + s * 8;
        uint32_t dst = sb + FL_SMKV + s * FL_STAGE;
        size_t go = ((size_t)(bh * 8 + j)) << 14;
        mbar_expect_tx(mb, FL_STAGE);
        bulk_g2s(dst,         K0 + go, TILE_BYTES, mb);
        bulk_g2s(dst + 16384, K1 + go, TILE_BYTES, mb);
        bulk_g2s(dst + 32768, V0 + go, TILE_BYTES, mb);
        bulk_g2s(dst + 49152, V1 + go, TILE_BYTES, mb);
    };

    if (tid == 0) {
        mbar_expect_tx(sb + 16, 65536);
#pragma unroll
        for (int h = 0; h < 2; h++) {
            size_t qo = ((size_t)(bh * 8 + qb2 * 2 + h)) << 14;
            bulk_g2s(sb + FL_SMQ + h * 32768,         Q0 + qo, TILE_BYTES, sb + 16);
            bulk_g2s(sb + FL_SMQ + h * 32768 + 16384, Q1 + qo, TILE_BYTES, sb + 16);
        }
        load_chunk(0, 0);
        load_chunk(1, 1);
    }
    mbar_wait(sb + 16, 0);

    float acc_o[2][8][4];
#pragma unroll
    for (int h = 0; h < 2; h++)
#pragma unroll
        for (int i = 0; i < 8; i++)
#pragma unroll
            for (int q = 0; q < 4; q++) acc_o[h][i][q] = 0.f;
    float mM[2][2] = {{-1e30f, -1e30f}, {-1e30f, -1e30f}};
    float lL[2][2] = {{0.f, 0.f}, {0.f, 0.f}};

    int a_row = wid * 16 + (lane & 15);
    int a_ks  = (lane >> 4) << 4;
    int b_nr = (lane >> 4) * 8 + (lane & 7);
    int b_ks = ((lane >> 3) & 1) << 4;
    int v_row = lane & 15;
    int v_cs  = (lane >> 4) << 4;

    for (int j = 0; j < 8; j++) {
        int s = j & 1;
        mbar_wait(sb + s * 8, (j >> 1) & 1);
        uint32_t kb = sb + FL_SMKV + s * FL_STAGE;
        uint32_t vb = kb + 32768;

#pragma unroll 1
        for (int qh = 0; qh < 2; qh++) {
            uint32_t qbase = sb + FL_SMQ + qh * 32768;
            uint32_t aQ0[4][4], aQ1[4][4];
#pragma unroll
            for (int ks = 0; ks < 4; ks++) {
                uint32_t off = sw128((uint32_t)a_row * 128 + ks * 32 + a_ks);
                ldsm4(aQ0[ks], qbase + off);
                ldsm4(aQ1[ks], qbase + 16384 + off);
            }

            float p[16][4];
#pragma unroll
            for (int i = 0; i < 16; i++)
#pragma unroll
                for (int q = 0; q < 4; q++) p[i][q] = 0.f;

#pragma unroll
            for (int nt = 0; nt < 8; nt++) {
#pragma unroll
                for (int ks = 0; ks < 4; ks++) {
                    uint32_t off = sw128((uint32_t)(nt * 16 + b_nr) * 128 + ks * 32 + b_ks);
                    uint32_t khi[4], klo[4];
                    ldsm4(khi, kb + off);
                    ldsm4(klo, kb + 16384 + off);
#pragma unroll
                    for (int nf = 0; nf < 2; nf++)
                        mma16816(p[nt * 2 + nf], aQ0[ks], khi + 2 * nf);
#pragma unroll
                    for (int nf = 0; nf < 2; nf++)
                        mma16816(p[nt * 2 + nf], aQ0[ks], klo + 2 * nf);
#pragma unroll
                    for (int nf = 0; nf < 2; nf++)
                        mma16816(p[nt * 2 + nf], aQ1[ks], khi + 2 * nf);
                }
            }

            float cm0 = -1e30f, cm1 = -1e30f;
#pragma unroll
            for (int i = 0; i < 16; i++) {
                cm0 = fmaxf(cm0, fmaxf(p[i][0], p[i][1]));
                cm1 = fmaxf(cm1, fmaxf(p[i][2], p[i][3]));
            }
            cm0 = fmaxf(cm0, __shfl_xor_sync(0xffffffffu, cm0, 1));
            cm0 = fmaxf(cm0, __shfl_xor_sync(0xffffffffu, cm0, 2));
            cm1 = fmaxf(cm1, __shfl_xor_sync(0xffffffffu, cm1, 1));
            cm1 = fmaxf(cm1, __shfl_xor_sync(0xffffffffu, cm1, 2));
            float mn0 = fmaxf(mM[qh][0], cm0 * SCALE_LOG2E);
            float mn1 = fmaxf(mM[qh][1], cm1 * SCALE_LOG2E);
            float al0 = ex2(mM[qh][0] - mn0), al1 = ex2(mM[qh][1] - mn1);
            mM[qh][0] = mn0; mM[qh][1] = mn1;

            float sum0 = 0.f, sum1 = 0.f;
#pragma unroll
            for (int i = 0; i < 16; i++) {
                p[i][0] = ex2(p[i][0] * SCALE_LOG2E - mn0); sum0 += p[i][0];
                p[i][1] = ex2(p[i][1] * SCALE_LOG2E - mn0); sum0 += p[i][1];
                p[i][2] = ex2(p[i][2] * SCALE_LOG2E - mn1); sum1 += p[i][2];
                p[i][3] = ex2(p[i][3] * SCALE_LOG2E - mn1); sum1 += p[i][3];
            }
            sum0 += __shfl_xor_sync(0xffffffffu, sum0, 1);
            sum0 += __shfl_xor_sync(0xffffffffu, sum0, 2);
            sum1 += __shfl_xor_sync(0xffffffffu, sum1, 1);
            sum1 += __shfl_xor_sync(0xffffffffu, sum1, 2);
            lL[qh][0] = al0 * lL[qh][0] + sum0;
            lL[qh][1] = al1 * lL[qh][1] + sum1;

#pragma unroll
            for (int i = 0; i < 8; i++) {
                acc_o[qh][i][0] *= al0; acc_o[qh][i][1] *= al0;
                acc_o[qh][i][2] *= al1; acc_o[qh][i][3] *= al1;
            }

#pragma unroll
            for (int kk = 0; kk < 8; kk++) {
                uint32_t ahi[4], alo[4];
                ahi[0] = bpack_hi(p[kk*2][0],   p[kk*2][1]);
                alo[0] = bpack_lo(p[kk*2][0],   p[kk*2][1]);
                ahi[1] = bpack_hi(p[kk*2][2],   p[kk*2][3]);
                alo[1] = bpack_lo(p[kk*2][2],   p[kk*2][3]);
                ahi[2] = bpack_hi(p[kk*2+1][0], p[kk*2+1][1]);
                alo[2] = bpack_lo(p[kk*2+1][0], p[kk*2+1][1]);
                ahi[3] = bpack_hi(p[kk*2+1][2], p[kk*2+1][3]);
                alo[3] = bpack_lo(p[kk*2+1][2], p[kk*2+1][3]);
#pragma unroll
                for (int vt = 0; vt < 4; vt++) {
                    uint32_t off = sw128((uint32_t)(kk * 16 + v_row) * 128 + vt * 32 + v_cs);
                    uint32_t vhi[4], vlo[4];
                    ldsm4t(vhi, vb + off);
                    ldsm4t(vlo, vb + 16384 + off);
#pragma unroll
                    for (int nf = 0; nf < 2; nf++)
                        mma16816(acc_o[qh][vt * 2 + nf], ahi, vhi + 2 * nf);
#pragma unroll
                    for (int nf = 0; nf < 2; nf++)
                        mma16816(acc_o[qh][vt * 2 + nf], ahi, vlo + 2 * nf);
#pragma unroll
                    for (int nf = 0; nf < 2; nf++)
                        mma16816(acc_o[qh][vt * 2 + nf], alo, vhi + 2 * nf);
                }
            }
        }
        __syncthreads();
        if (tid == 0 && j + 2 < 8) load_chunk(j + 2, s);
    }

    int bb = bh >> 4, hh = bh & 15;
#pragma unroll
    for (int qh = 0; qh < 2; qh++) {
        float inv0 = 1.f / lL[qh][0], inv1 = 1.f / lL[qh][1];
        int grow = bb * SEQ + qb2 * 256 + qh * 128 + wid * 16 + (lane >> 2);
#pragma unroll
        for (int f = 0; f < 8; f++) {
            int col = hh * 64 + f * 8 + (lane & 3) * 2;
            float x0 = acc_o[qh][f][0] * inv0, y0 = acc_o[qh][f][1] * inv0;
            float x1 = acc_o[qh][f][2] * inv1, y1 = acc_o[qh][f][3] * inv1;
            size_t po0 = packed_off(grow, col, DIM);
            size_t po1 = packed_off(grow + 8, col, DIM);
            *reinterpret_cast<uint32_t*>(O0 + po0) = bpack_hi(x0, y0);
            *reinterpret_cast<uint32_t*>(O1 + po0) = bpack_lo(x0, y0);
            *reinterpret_cast<uint32_t*>(O0 + po1) = bpack_hi(x1, y1);
            *reinterpret_cast<uint32_t*>(O1 + po1) = bpack_lo(x1, y1);
        }
    }
}

// ------------------------- reductions -------------------------
__device__ __forceinline__ float warp_sum(float v) {
#pragma unroll
    for (int o = 16; o; o >>= 1) v += __shfl_xor_sync(0xffffffffu, v, o);
    return v;
}

// ------------------------- layernorm -> packed bf16 splits -------------------------
__global__ __launch_bounds__(256) void ln_split_kernel(
    const float* __restrict__ X, const float* __restrict__ G,
    const float* __restrict__ B, char* __restrict__ Y0, char* __restrict__ Y1)
{
    __shared__ float red[8];
    int row = blockIdx.x;
    int tid = threadIdx.x;
    int lane = tid & 31, wid = tid >> 5;

    float4 v = reinterpret_cast<const float4*>(X + (size_t)row * DIM)[tid];
    float s = v.x + v.y + v.z + v.w;
    s = warp_sum(s);
    if (lane == 0) red[wid] = s;
    __syncthreads();
    if (wid == 0) {
        float t = (lane < 8) ? red[lane] : 0.f;
        t = warp_sum(t);
        if (lane == 0) red[0] = t;
    }
    __syncthreads();
    float mu = red[0] * (1.0f / DIM);
    __syncthreads();

    float4 d;
    d.x = v.x - mu; d.y = v.y - mu; d.z = v.z - mu; d.w = v.w - mu;
    float sq = d.x*d.x + d.y*d.y + d.z*d.z + d.w*d.w;
    sq = warp_sum(sq);
    if (lane == 0) red[wid] = sq;
    __syncthreads();
    if (wid == 0) {
        float t = (lane < 8) ? red[lane] : 0.f;
        t = warp_sum(t);
        if (lane == 0) red[0] = t;
    }
    __syncthreads();
    float rs = rsqrtf(red[0] * (1.0f / DIM) + 1e-5f);

    float4 g4 = reinterpret_cast<const float4*>(G)[tid];
    float4 b4 = reinterpret_cast<const float4*>(B)[tid];
    float y[4];
    y[0] = d.x * rs * g4.x + b4.x;
    y[1] = d.y * rs * g4.y + b4.y;
    y[2] = d.z * rs * g4.z + b4.z;
    y[3] = d.w * rs * g4.w + b4.w;

    size_t po = packed_off(row, tid * 4, DIM);
    uint32_t h0 = bpack_hi(y[0], y[1]), h1 = bpack_hi(y[2], y[3]);
    uint32_t l0 = bpack_lo(y[0], y[1]), l1 = bpack_lo(y[2], y[3]);
    *reinterpret_cast<uint2*>(Y0 + po) = make_uint2(h0, h1);
    *reinterpret_cast<uint2*>(Y1 + po) = make_uint2(l0, l1);
}

// ------------------------- weight transpose + split (dual-tensor) -------------------------
// z=1 uses swapped block indexing so rectangular grids fit both tensors exactly.
__global__ __launch_bounds__(256) void wsplit_dual(
    const float* __restrict__ Wa, char* __restrict__ T0a, char* __restrict__ T1a,
    int Ka, int Na,
    const float* __restrict__ Wb, char* __restrict__ T0b, char* __restrict__ T1b,
    int Kb, int Nb)
{
    const float* W; char* T0; char* T1; int K, N, n0, k0;
    if (blockIdx.z == 0) {
        W = Wa; T0 = T0a; T1 = T1a; K = Ka; N = Na;
        n0 = blockIdx.x * 32; k0 = blockIdx.y * 32;
    } else {
        W = Wb; T0 = T0b; T1 = T1b; K = Kb; N = Nb;
        n0 = blockIdx.y * 32; k0 = blockIdx.x * 32;
    }
    if (n0 >= N || k0 >= K) return;

    __shared__ float t[32][33];
    int c = threadIdx.x & 31, r = threadIdx.x >> 5;
#pragma unroll
    for (int rr = 0; rr < 32; rr += 8)
        t[r + rr][c] = W[(size_t)(k0 + r + rr) * N + n0 + c];
    __syncthreads();
    int tx = threadIdx.x & 7;
    int ty = threadIdx.x >> 3;
    int n = n0 + ty, k = k0 + tx * 4;
    float v0 = t[tx*4+0][ty], v1 = t[tx*4+1][ty], v2 = t[tx*4+2][ty], v3 = t[tx*4+3][ty];
    size_t po = packed_off(n, k, K);
    *reinterpret_cast<uint2*>(T0 + po) = make_uint2(bpack_hi(v0, v1), bpack_hi(v2, v3));
    *reinterpret_cast<uint2*>(T1 + po) = make_uint2(bpack_lo(v0, v1), bpack_lo(v2, v3));
}

// ------------------------- launch -------------------------
extern "C" void kernel_launch(void* const* d_in, const int* in_sizes, int n_in,
                              void* d_out, int out_size)
{
    const float* x     = (const float*)d_in[0];
    const float* ln1_g = (const float*)d_in[1];
    const float* ln1_b = (const float*)d_in[2];
    const float* w_qkv = (const float*)d_in[3];
    const float* w_o   = (const float*)d_in[4];
    const float* b_o   = (const float*)d_in[5];
    const float* ln2_g = (const float*)d_in[6];
    const float* ln2_b = (const float*)d_in[7];
    const float* w1    = (const float*)d_in[8];
    const float* b1    = (const float*)d_in[9];
    const float* w2    = (const float*)d_in[10];
    const float* b2    = (const float*)d_in[11];

    float *gx;
    char *a0, *a1, *h0, *h1, *q0, *q1, *k0, *k1, *v0, *v1;
    char *wq0, *wq1, *wo0, *wo1, *w10, *w11, *w20, *w21;
    cudaGetSymbolAddress((void**)&gx,  g_x);
    cudaGetSymbolAddress((void**)&a0,  g_a0);
    cudaGetSymbolAddress((void**)&a1,  g_a1);
    cudaGetSymbolAddress((void**)&h0,  g_h0);
    cudaGetSymbolAddress((void**)&h1,  g_h1);
    cudaGetSymbolAddress((void**)&q0,  g_q0);
    cudaGetSymbolAddress((void**)&q1,  g_q1);
    cudaGetSymbolAddress((void**)&k0,  g_k0);
    cudaGetSymbolAddress((void**)&k1,  g_k1);
    cudaGetSymbolAddress((void**)&v0,  g_v0);
    cudaGetSymbolAddress((void**)&v1,  g_v1);
    cudaGetSymbolAddress((void**)&wq0, g_wq0);
    cudaGetSymbolAddress((void**)&wq1, g_wq1);
    cudaGetSymbolAddress((void**)&wo0, g_wo0);
    cudaGetSymbolAddress((void**)&wo1, g_wo1);
    cudaGetSymbolAddress((void**)&w10, g_w10);
    cudaGetSymbolAddress((void**)&w11, g_w11);
    cudaGetSymbolAddress((void**)&w20, g_w20);
    cudaGetSymbolAddress((void**)&w21, g_w21);

    cudaFuncSetAttribute(gemm_tc, cudaFuncAttributeMaxDynamicSharedMemorySize, SM_TOTAL);
    cudaFuncSetAttribute(flash_kernel, cudaFuncAttributeMaxDynamicSharedMemorySize, FL_TOTAL);

    wsplit_dual<<<dim3(96, 32, 2), 256>>>(w_qkv, wq0, wq1, DIM, 3 * DIM,
                                          w_o, wo0, wo1, DIM, DIM);
    wsplit_dual<<<dim3(128, 32, 2), 256>>>(w1, w10, w11, DIM, MLPD,
                                           w2, w20, w21, MLPD, DIM);

    for (int layer = 0; layer < 4; layer++) {
        const float* xin = (layer == 0) ? x : gx;

        // --- attention ---
        ln_split_kernel<<<RTOK, 256>>>(xin, ln1_g, ln1_b, a0, a1);
        gemm_tc<<<dim3(3 * DIM / 128, RTOK / 128), 256, SM_TOTAL>>>(
            a0, a1, wq0, wq1, nullptr, nullptr, nullptr, q0, q1,
            k0, k1, v0, v1, 3 * DIM, DIM, 3);
        flash_kernel<<<dim3(4, NBH), 256, FL_TOTAL>>>(
            q0, q1, k0, k1, v0, v1, a0, a1);
        gemm_tc<<<dim3(DIM / 128, RTOK / 128), 256, SM_TOTAL>>>(
            a0, a1, wo0, wo1, b_o, xin, gx, nullptr, nullptr,
            nullptr, nullptr, nullptr, nullptr, DIM, DIM, 1);

        // --- MLP ---
        ln_split_kernel<<<RTOK, 256>>>(gx, ln2_g, ln2_b, a0, a1);
        gemm_tc<<<dim3(MLPD / 128, RTOK / 128), 256, SM_TOTAL>>>(
            a0, a1, w10, w11, b1, nullptr, nullptr, h0, h1,
            nullptr, nullptr, nullptr, nullptr, MLPD, DIM, 2);
        float* outp = (layer == 3) ? (float*)d_out : gx;
        gemm_tc<<<dim3(DIM / 128, RTOK / 128), 256, SM_TOTAL>>>(
            h0, h1, w20, w21, b2, gx, outp, nullptr, nullptr,
            nullptr, nullptr, nullptr, nullptr, DIM, MLPD, 1);
    }
}

// round 12
// speedup vs baseline: 1.4094x; 1.4094x over previous
#include <cuda_runtime.h>
#include <cuda_fp16.h>
#include <math.h>
#include <stdint.h>

#define RTOK 2048
#define DIM  1024
#define NH   16
#define HDIM 64
#define MLPD 4096
#define NBH  32
#define SEQ  1024

// ------------------------- scratch (device globals) -------------------------
__device__ float g_x[RTOK * DIM];
__device__ __align__(128) __half g_a0[RTOK * DIM],  g_a1[RTOK * DIM];
__device__ __align__(128) __half g_h0[RTOK * MLPD], g_h1[RTOK * MLPD];
__device__ __align__(128) __half g_q0[RTOK * DIM],  g_q1[RTOK * DIM];
__device__ __align__(128) __half g_k0[RTOK * DIM];
__device__ __align__(128) __half g_v0[RTOK * DIM];
__device__ __align__(128) __half g_wq0[3*DIM*DIM];
__device__ __align__(128) __half g_wo0[DIM*DIM];
__device__ __align__(128) __half g_w10[MLPD*DIM];
__device__ __align__(128) __half g_w20[DIM*MLPD];

// ------------------------- helpers -------------------------
__device__ __forceinline__ uint32_t smem_u32(const void* p) {
    uint32_t a;
    asm("{ .reg .u64 t; cvta.to.shared.u64 t, %1; cvt.u32.u64 %0, t; }" : "=r"(a) : "l"(p));
    return a;
}
__device__ __forceinline__ uint32_t sw128(uint32_t off) { return off ^ ((off >> 3) & 0x70); }

__device__ __forceinline__ size_t packed_off(int row, int col, int K) {
    int rb = row >> 7, kc = col >> 6;
    uint32_t off = ((uint32_t)(row & 127) << 7) | ((uint32_t)(col & 63) << 1);
    off = off ^ ((off >> 3) & 0x70);
    return ((size_t)(rb * (K >> 6) + kc) << 14) + off;
}

__device__ __forceinline__ void mbar_init(uint32_t a, uint32_t cnt) {
    asm volatile("mbarrier.init.shared.b64 [%0], %1;" :: "r"(a), "r"(cnt) : "memory");
}
__device__ __forceinline__ void mbar_expect_tx(uint32_t a, uint32_t bytes) {
    asm volatile("mbarrier.arrive.expect_tx.shared.b64 _, [%0], %1;" :: "r"(a), "r"(bytes) : "memory");
}
__device__ __forceinline__ void mbar_wait(uint32_t a, uint32_t parity) {
    asm volatile(
        "{\n\t.reg .pred P1;\n\t"
        "LAB_WAIT_%=:\n\t"
        "mbarrier.try_wait.parity.acquire.cta.shared::cta.b64 P1, [%0], %1, 0x989680;\n\t"
        "@P1 bra.uni LAB_DONE_%=;\n\t"
        "bra.uni LAB_WAIT_%=;\n\t"
        "LAB_DONE_%=:\n\t}"
        :: "r"(a), "r"(parity) : "memory");
}
__device__ __forceinline__ void bulk_g2s(uint32_t dst, const void* src, uint32_t bytes, uint32_t mbar) {
    asm volatile(
        "cp.async.bulk.shared::cta.global.mbarrier::complete_tx::bytes [%0], [%1], %2, [%3];"
        :: "r"(dst), "l"(src), "r"(bytes), "r"(mbar) : "memory");
}
__device__ __forceinline__ void ldsm4(uint32_t* r, uint32_t addr) {
    asm volatile("ldmatrix.sync.aligned.m8n8.x4.shared.b16 {%0,%1,%2,%3}, [%4];"
                 : "=r"(r[0]), "=r"(r[1]), "=r"(r[2]), "=r"(r[3]) : "r"(addr));
}
__device__ __forceinline__ void ldsm4t(uint32_t* r, uint32_t addr) {
    asm volatile("ldmatrix.sync.aligned.m8n8.x4.trans.shared.b16 {%0,%1,%2,%3}, [%4];"
                 : "=r"(r[0]), "=r"(r[1]), "=r"(r[2]), "=r"(r[3]) : "r"(addr));
}
__device__ __forceinline__ void mma16816(float* c, const uint32_t* a, const uint32_t* b) {
    asm volatile(
        "mma.sync.aligned.m16n8k16.row.col.f32.f16.f16.f32 "
        "{%0,%1,%2,%3}, {%4,%5,%6,%7}, {%8,%9}, {%0,%1,%2,%3};"
        : "+f"(c[0]), "+f"(c[1]), "+f"(c[2]), "+f"(c[3])
        : "r"(a[0]), "r"(a[1]), "r"(a[2]), "r"(a[3]), "r"(b[0]), "r"(b[1]));
}
__device__ __forceinline__ float ex2(float x) {
    float y; asm("ex2.approx.f32 %0, %1;" : "=f"(y) : "f"(x)); return y;
}
__device__ __forceinline__ uint32_t hpack_hi(float x, float y) {
    __half2 t(__float2half_rn(x), __float2half_rn(y));
    return *reinterpret_cast<uint32_t*>(&t);
}
__device__ __forceinline__ uint32_t hpack_lo(float x, float y) {
    float hx = __half2float(__float2half_rn(x));
    float hy = __half2float(__float2half_rn(y));
    __half2 t(__float2half_rn(x - hx), __float2half_rn(y - hy));
    return *reinterpret_cast<uint32_t*>(&t);
}

#define TILE_BYTES  16384
#define G_STAGE     49152
#define SM_TILES    1024
#define NSTAGE      3
#define SM_TOTAL    (SM_TILES + NSTAGE * G_STAGE)

// ------------------- fp16 split-2 tensor GEMM 128x128 (R6 structure) -------------------
// C = (A0+A1)[M,K] @ B^T, B plain fp16 packed [N,K].
// epi: 0 fp32; 1 +bias+Res fp32; 2 +bias GELU -> packed fp16 hi/lo; 3 QKV per-head
__global__ __launch_bounds__(256, 1) void gemm_tc(
    const char* __restrict__ A0, const char* __restrict__ A1,
    const char* __restrict__ B,
    const float* __restrict__ bias, const float* __restrict__ Res,
    float* __restrict__ Cf, char* __restrict__ C0, char* __restrict__ C1,
    char* __restrict__ K0o, char* __restrict__ V0o,
    int N, int K, int epi)
{
    extern __shared__ char smem[];
    uint32_t sb = smem_u32(smem);
    int tid = threadIdx.x, wid = tid >> 5, lane = tid & 31;
    int m0 = blockIdx.y * 128, n0 = blockIdx.x * 128;
    int warp_m = (wid >> 1) * 32, warp_n = (wid & 1) * 64;
    const int NC = K >> 6;

    if (tid == 0) { mbar_init(sb, 1); mbar_init(sb + 8, 1); mbar_init(sb + 16, 1); }
    __syncthreads();

    size_t abase = ((size_t)((m0 >> 7) * NC)) << 14;
    size_t bbase = ((size_t)((n0 >> 7) * NC)) << 14;

    auto load_chunk = [&](int c, int s) {
        uint32_t mb = sb + s * 8;
        uint32_t dst = sb + SM_TILES + s * G_STAGE;
        size_t go = (size_t)c << 14;
        mbar_expect_tx(mb, G_STAGE);
        bulk_g2s(dst,                 A0 + abase + go, TILE_BYTES, mb);
        bulk_g2s(dst + TILE_BYTES,    A1 + abase + go, TILE_BYTES, mb);
        bulk_g2s(dst + 2*TILE_BYTES,  B  + bbase + go, TILE_BYTES, mb);
    };

    if (tid == 0) { load_chunk(0, 0); load_chunk(1, 1); }

    float acc[2][8][4];
#pragma unroll
    for (int i = 0; i < 2; i++)
#pragma unroll
        for (int j = 0; j < 8; j++)
#pragma unroll
            for (int q = 0; q < 4; q++) acc[i][j][q] = 0.f;

    int a_row = warp_m + (lane & 15);
    int a_ks  = (lane >> 4) << 4;
    int b_nr  = warp_n + ((lane >> 4) << 3) + (lane & 7);
    int b_ks  = ((lane >> 3) & 1) << 4;

    int stage = 0, phase = 0;
    for (int c = 0; c < NC; c++) {
        mbar_wait(sb + stage * 8, phase);
        if (tid == 0 && c + 2 < NC) {
            int s2 = stage + 2; if (s2 >= NSTAGE) s2 -= NSTAGE;
            load_chunk(c + 2, s2);
        }

        uint32_t base = sb + SM_TILES + stage * G_STAGE;
#pragma unroll
        for (int ks = 0; ks < 4; ks++) {
            uint32_t aA[2][2][4];
#pragma unroll
            for (int mi = 0; mi < 2; mi++) {
                uint32_t off = sw128((uint32_t)(a_row + mi * 16) * 128 + ks * 32 + a_ks);
                ldsm4(aA[mi][0], base + off);
                ldsm4(aA[mi][1], base + TILE_BYTES + off);
            }
#pragma unroll
            for (int nj = 0; nj < 4; nj++) {
                uint32_t boff = sw128((uint32_t)(b_nr + nj * 16) * 128 + ks * 32 + b_ks);
                uint32_t bfr[4];
                ldsm4(bfr, base + 2 * TILE_BYTES + boff);
                // split-major: all hi-products, then all lo-products (dep distance 4)
#pragma unroll
                for (int mi = 0; mi < 2; mi++)
#pragma unroll
                    for (int nf = 0; nf < 2; nf++)
                        mma16816(acc[mi][nj * 2 + nf], aA[mi][0], bfr + 2 * nf);
#pragma unroll
                for (int mi = 0; mi < 2; mi++)
#pragma unroll
                    for (int nf = 0; nf < 2; nf++)
                        mma16816(acc[mi][nj * 2 + nf], aA[mi][1], bfr + 2 * nf);
            }
        }
        __syncthreads();
        if (++stage == NSTAGE) { stage = 0; phase ^= 1; }
    }

    int mrow = m0 + warp_m + (lane >> 2);
    int ncol = n0 + warp_n + (lane & 3) * 2;
#pragma unroll
    for (int mi = 0; mi < 2; mi++) {
#pragma unroll
        for (int nj = 0; nj < 8; nj++) {
#pragma unroll
            for (int h = 0; h < 2; h++) {
                int m = mrow + mi * 16 + h * 8;
                int n = ncol + nj * 8;
                float v0 = acc[mi][nj][2 * h];
                float v1 = acc[mi][nj][2 * h + 1];
                if (epi == 0) {
                    *reinterpret_cast<float2*>(Cf + (size_t)m * N + n) = make_float2(v0, v1);
                } else if (epi == 1) {
                    size_t off = (size_t)m * N + n;
                    float2 r = *reinterpret_cast<const float2*>(Res + off);
                    *reinterpret_cast<float2*>(Cf + off) =
                        make_float2(v0 + bias[n] + r.x, v1 + bias[n + 1] + r.y);
                } else if (epi == 2) {
                    float t0 = v0 + bias[n],     t1 = v1 + bias[n + 1];
                    float g0 = 0.5f * t0 * (1.0f + erff(t0 * 0.70710678118654752f));
                    float g1 = 0.5f * t1 * (1.0f + erff(t1 * 0.70710678118654752f));
                    size_t po = packed_off(m, n, N);
                    *reinterpret_cast<uint32_t*>(C0 + po) = hpack_hi(g0, g1);
                    *reinterpret_cast<uint32_t*>(C1 + po) = hpack_lo(g0, g1);
                } else {
                    int sel = n >> 10;
                    int hh  = (n >> 6) & 15;
                    int d   = n & 63;
                    int bb  = m >> 10;
                    int qq  = m & 1023;
                    int blk = ((bb * 16 + hh) * 8) + (qq >> 7);
                    uint32_t off = (uint32_t)(qq & 127) * 128 + d * 2;
                    off ^= (off >> 3) & 0x70;
                    size_t po = ((size_t)blk << 14) + off;
                    if (sel == 0) {
                        *reinterpret_cast<uint32_t*>(C0 + po) = hpack_hi(v0, v1);
                        *reinterpret_cast<uint32_t*>(C1 + po) = hpack_lo(v0, v1);
                    } else if (sel == 1) {
                        *reinterpret_cast<uint32_t*>(K0o + po) = hpack_hi(v0, v1);
                    } else {
                        *reinterpret_cast<uint32_t*>(V0o + po) = hpack_hi(v0, v1);
                    }
                }
            }
        }
    }
}

// ------------------------- flash attention (R6 structure, fp16 split-2) ----------------
#define FL_STAGE 32768
#define FL_SMQ   1024
#define FL_SMKV  (1024 + 32768)
#define FL_TOTAL (1024 + 32768 + 3 * 32768)

__global__ __launch_bounds__(256, 1) void flash_kernel(
    const char* __restrict__ Q0, const char* __restrict__ Q1,
    const char* __restrict__ K0, const char* __restrict__ V0,
    char* __restrict__ O0, char* __restrict__ O1)
{
    extern __shared__ char smem[];
    uint32_t sb = smem_u32(smem);
    int tid = threadIdx.x, wid = tid >> 5, lane = tid & 31;
    int qb = blockIdx.x, bh = blockIdx.y;
    const float SCALE_LOG2E = 0.03125f * 1.44269504088896341f;

    if (tid == 0) {
        mbar_init(sb, 1); mbar_init(sb + 8, 1); mbar_init(sb + 16, 1); mbar_init(sb + 24, 1);
    }
    __syncthreads();

    auto load_chunk = [&](int j, int s) {
        uint32_t mb = sb + s * 8;
        uint32_t dst = sb + FL_SMKV + s * FL_STAGE;
        size_t go = ((size_t)(bh * 8 + j)) << 14;
        mbar_expect_tx(mb, FL_STAGE);
        bulk_g2s(dst,         K0 + go, TILE_BYTES, mb);
        bulk_g2s(dst + 16384, V0 + go, TILE_BYTES, mb);
    };

    if (tid == 0) {
        size_t qo = ((size_t)(bh * 8 + qb)) << 14;
        mbar_expect_tx(sb + 24, 32768);
        bulk_g2s(sb + FL_SMQ,         Q0 + qo, TILE_BYTES, sb + 24);
        bulk_g2s(sb + FL_SMQ + 16384, Q1 + qo, TILE_BYTES, sb + 24);
        load_chunk(0, 0);
        load_chunk(1, 1);
    }

    mbar_wait(sb + 24, 0);
    uint32_t aQ0[4][4], aQ1[4][4];
    {
        int a_row = wid * 16 + (lane & 15);
        int a_ks  = (lane >> 4) << 4;
#pragma unroll
        for (int ks = 0; ks < 4; ks++) {
            uint32_t off = sw128((uint32_t)a_row * 128 + ks * 32 + a_ks);
            ldsm4(aQ0[ks], sb + FL_SMQ + off);
            ldsm4(aQ1[ks], sb + FL_SMQ + 16384 + off);
        }
    }

    float acc_o[8][4];
#pragma unroll
    for (int i = 0; i < 8; i++)
#pragma unroll
        for (int q = 0; q < 4; q++) acc_o[i][q] = 0.f;
    float m0 = -1e30f, m1 = -1e30f, l0 = 0.f, l1 = 0.f;

    int b_nr = (lane >> 4) * 8 + (lane & 7);
    int b_ks = ((lane >> 3) & 1) << 4;
    int v_row = lane & 15;
    int v_cs  = (lane >> 4) << 4;

    int stage = 0, phase = 0;
    for (int j = 0; j < 8; j++) {
        mbar_wait(sb + stage * 8, phase);
        if (tid == 0 && j + 2 < 8) {
            int s2 = stage + 2; if (s2 >= NSTAGE) s2 -= NSTAGE;
            load_chunk(j + 2, s2);
        }

        uint32_t kb = sb + FL_SMKV + stage * FL_STAGE;
        uint32_t vb = kb + 16384;

        float p[16][4];
#pragma unroll
        for (int i = 0; i < 16; i++)
#pragma unroll
            for (int q = 0; q < 4; q++) p[i][q] = 0.f;

#pragma unroll
        for (int nt = 0; nt < 8; nt++) {
#pragma unroll
            for (int ks = 0; ks < 4; ks++) {
                uint32_t off = sw128((uint32_t)(nt * 16 + b_nr) * 128 + ks * 32 + b_ks);
                uint32_t kfr[4];
                ldsm4(kfr, kb + off);
#pragma unroll
                for (int nf = 0; nf < 2; nf++)
                    mma16816(p[nt * 2 + nf], aQ0[ks], kfr + 2 * nf);
#pragma unroll
                for (int nf = 0; nf < 2; nf++)
                    mma16816(p[nt * 2 + nf], aQ1[ks], kfr + 2 * nf);
            }
        }

        float cm0 = -1e30f, cm1 = -1e30f;
#pragma unroll
        for (int i = 0; i < 16; i++) {
            cm0 = fmaxf(cm0, fmaxf(p[i][0], p[i][1]));
            cm1 = fmaxf(cm1, fmaxf(p[i][2], p[i][3]));
        }
        cm0 = fmaxf(cm0, __shfl_xor_sync(0xffffffffu, cm0, 1));
        cm0 = fmaxf(cm0, __shfl_xor_sync(0xffffffffu, cm0, 2));
        cm1 = fmaxf(cm1, __shfl_xor_sync(0xffffffffu, cm1, 1));
        cm1 = fmaxf(cm1, __shfl_xor_sync(0xffffffffu, cm1, 2));
        float mn0 = fmaxf(m0, cm0 * SCALE_LOG2E);
        float mn1 = fmaxf(m1, cm1 * SCALE_LOG2E);
        float al0 = ex2(m0 - mn0), al1 = ex2(m1 - mn1);
        m0 = mn0; m1 = mn1;

        float sum0 = 0.f, sum1 = 0.f;
#pragma unroll
        for (int i = 0; i < 16; i++) {
            p[i][0] = ex2(p[i][0] * SCALE_LOG2E - m0); sum0 += p[i][0];
            p[i][1] = ex2(p[i][1] * SCALE_LOG2E - m0); sum0 += p[i][1];
            p[i][2] = ex2(p[i][2] * SCALE_LOG2E - m1); sum1 += p[i][2];
            p[i][3] = ex2(p[i][3] * SCALE_LOG2E - m1); sum1 += p[i][3];
        }
        sum0 += __shfl_xor_sync(0xffffffffu, sum0, 1);
        sum0 += __shfl_xor_sync(0xffffffffu, sum0, 2);
        sum1 += __shfl_xor_sync(0xffffffffu, sum1, 1);
        sum1 += __shfl_xor_sync(0xffffffffu, sum1, 2);
        l0 = al0 * l0 + sum0;
        l1 = al1 * l1 + sum1;

#pragma unroll
        for (int i = 0; i < 8; i++) {
            acc_o[i][0] *= al0; acc_o[i][1] *= al0;
            acc_o[i][2] *= al1; acc_o[i][3] *= al1;
        }

#pragma unroll
        for (int kk = 0; kk < 8; kk++) {
            uint32_t phi[4], plo[4];
            phi[0] = hpack_hi(p[kk*2][0],   p[kk*2][1]);
            plo[0] = hpack_lo(p[kk*2][0],   p[kk*2][1]);
            phi[1] = hpack_hi(p[kk*2][2],   p[kk*2][3]);
            plo[1] = hpack_lo(p[kk*2][2],   p[kk*2][3]);
            phi[2] = hpack_hi(p[kk*2+1][0], p[kk*2+1][1]);
            plo[2] = hpack_lo(p[kk*2+1][0], p[kk*2+1][1]);
            phi[3] = hpack_hi(p[kk*2+1][2], p[kk*2+1][3]);
            plo[3] = hpack_lo(p[kk*2+1][2], p[kk*2+1][3]);
#pragma unroll
            for (int vt = 0; vt < 4; vt++) {
                uint32_t off = sw128((uint32_t)(kk * 16 + v_row) * 128 + vt * 32 + v_cs);
                uint32_t vfr[4];
                ldsm4t(vfr, vb + off);
#pragma unroll
                for (int nf = 0; nf < 2; nf++)
                    mma16816(acc_o[vt * 2 + nf], phi, vfr + 2 * nf);
#pragma unroll
                for (int nf = 0; nf < 2; nf++)
                    mma16816(acc_o[vt * 2 + nf], plo, vfr + 2 * nf);
            }
        }
        __syncthreads();
        if (++stage == NSTAGE) { stage = 0; phase ^= 1; }
    }

    float inv0 = 1.f / l0, inv1 = 1.f / l1;
    int bb = bh >> 4, hh = bh & 15;
    int grow = bb * SEQ + qb * 128 + wid * 16 + (lane >> 2);
#pragma unroll
    for (int f = 0; f < 8; f++) {
        int col = hh * 64 + f * 8 + (lane & 3) * 2;
        float x0 = acc_o[f][0] * inv0, y0 = acc_o[f][1] * inv0;
        float x1 = acc_o[f][2] * inv1, y1 = acc_o[f][3] * inv1;
        size_t po0 = packed_off(grow, col, DIM);
        size_t po1 = packed_off(grow + 8, col, DIM);
        *reinterpret_cast<uint32_t*>(O0 + po0) = hpack_hi(x0, y0);
        *reinterpret_cast<uint32_t*>(O1 + po0) = hpack_lo(x0, y0);
        *reinterpret_cast<uint32_t*>(O0 + po1) = hpack_hi(x1, y1);
        *reinterpret_cast<uint32_t*>(O1 + po1) = hpack_lo(x1, y1);
    }
}

// ------------------------- reductions -------------------------
__device__ __forceinline__ float warp_sum(float v) {
#pragma unroll
    for (int o = 16; o; o >>= 1) v += __shfl_xor_sync(0xffffffffu, v, o);
    return v;
}

// ------------------------- layernorm -> packed fp16 hi/lo -------------------------
__global__ __launch_bounds__(256) void ln_split_kernel(
    const float* __restrict__ X, const float* __restrict__ G,
    const float* __restrict__ B, char* __restrict__ Y0, char* __restrict__ Y1)
{
    __shared__ float red[8];
    int row = blockIdx.x;
    int tid = threadIdx.x;
    int lane = tid & 31, wid = tid >> 5;

    float4 v = reinterpret_cast<const float4*>(X + (size_t)row * DIM)[tid];
    float s = v.x + v.y + v.z + v.w;
    s = warp_sum(s);
    if (lane == 0) red[wid] = s;
    __syncthreads();
    if (wid == 0) {
        float t = (lane < 8) ? red[lane] : 0.f;
        t = warp_sum(t);
        if (lane == 0) red[0] = t;
    }
    __syncthreads();
    float mu = red[0] * (1.0f / DIM);
    __syncthreads();

    float4 d;
    d.x = v.x - mu; d.y = v.y - mu; d.z = v.z - mu; d.w = v.w - mu;
    float sq = d.x*d.x + d.y*d.y + d.z*d.z + d.w*d.w;
    sq = warp_sum(sq);
    if (lane == 0) red[wid] = sq;
    __syncthreads();
    if (wid == 0) {
        float t = (lane < 8) ? red[lane] : 0.f;
        t = warp_sum(t);
        if (lane == 0) red[0] = t;
    }
    __syncthreads();
    float rs = rsqrtf(red[0] * (1.0f / DIM) + 1e-5f);

    float4 g4 = reinterpret_cast<const float4*>(G)[tid];
    float4 b4 = reinterpret_cast<const float4*>(B)[tid];
    float y[4];
    y[0] = d.x * rs * g4.x + b4.x;
    y[1] = d.y * rs * g4.y + b4.y;
    y[2] = d.z * rs * g4.z + b4.z;
    y[3] = d.w * rs * g4.w + b4.w;

    size_t po = packed_off(row, tid * 4, DIM);
    *reinterpret_cast<uint2*>(Y0 + po) = make_uint2(hpack_hi(y[0], y[1]), hpack_hi(y[2], y[3]));
    *reinterpret_cast<uint2*>(Y1 + po) = make_uint2(hpack_lo(y[0], y[1]), hpack_lo(y[2], y[3]));
}

// ------------------------- weight transpose -> plain fp16 packed ----------------------
__global__ __launch_bounds__(256) void wsplit_dual(
    const float* __restrict__ Wa, char* __restrict__ Ta, int Ka, int Na,
    const float* __restrict__ Wb, char* __restrict__ Tb, int Kb, int Nb)
{
    const float* W; char* T; int K, N, n0, k0;
    if (blockIdx.z == 0) {
        W = Wa; T = Ta; K = Ka; N = Na;
        n0 = blockIdx.x * 32; k0 = blockIdx.y * 32;
    } else {
        W = Wb; T = Tb; K = Kb; N = Nb;
        n0 = blockIdx.y * 32; k0 = blockIdx.x * 32;
    }
    if (n0 >= N || k0 >= K) return;

    __shared__ float t[32][33];
    int c = threadIdx.x & 31, r = threadIdx.x >> 5;
#pragma unroll
    for (int rr = 0; rr < 32; rr += 8)
        t[r + rr][c] = W[(size_t)(k0 + r + rr) * N + n0 + c];
    __syncthreads();
    int tx = threadIdx.x & 7;
    int ty = threadIdx.x >> 3;
    int n = n0 + ty, k = k0 + tx * 4;
    float v0 = t[tx*4+0][ty], v1 = t[tx*4+1][ty], v2 = t[tx*4+2][ty], v3 = t[tx*4+3][ty];
    size_t po = packed_off(n, k, K);
    *reinterpret_cast<uint2*>(T + po) = make_uint2(hpack_hi(v0, v1), hpack_hi(v2, v3));
}

// ------------------------- launch -------------------------
extern "C" void kernel_launch(void* const* d_in, const int* in_sizes, int n_in,
                              void* d_out, int out_size)
{
    const float* x     = (const float*)d_in[0];
    const float* ln1_g = (const float*)d_in[1];
    const float* ln1_b = (const float*)d_in[2];
    const float* w_qkv = (const float*)d_in[3];
    const float* w_o   = (const float*)d_in[4];
    const float* b_o   = (const float*)d_in[5];
    const float* ln2_g = (const float*)d_in[6];
    const float* ln2_b = (const float*)d_in[7];
    const float* w1    = (const float*)d_in[8];
    const float* b1    = (const float*)d_in[9];
    const float* w2    = (const float*)d_in[10];
    const float* b2    = (const float*)d_in[11];

    float *gx;
    char *a0, *a1, *h0, *h1, *q0, *q1, *k0, *v0;
    char *wq0, *wo0, *w10, *w20;
    cudaGetSymbolAddress((void**)&gx,  g_x);
    cudaGetSymbolAddress((void**)&a0,  g_a0);
    cudaGetSymbolAddress((void**)&a1,  g_a1);
    cudaGetSymbolAddress((void**)&h0,  g_h0);
    cudaGetSymbolAddress((void**)&h1,  g_h1);
    cudaGetSymbolAddress((void**)&q0,  g_q0);
    cudaGetSymbolAddress((void**)&q1,  g_q1);
    cudaGetSymbolAddress((void**)&k0,  g_k0);
    cudaGetSymbolAddress((void**)&v0,  g_v0);
    cudaGetSymbolAddress((void**)&wq0, g_wq0);
    cudaGetSymbolAddress((void**)&wo0, g_wo0);
    cudaGetSymbolAddress((void**)&w10, g_w10);
    cudaGetSymbolAddress((void**)&w20, g_w20);

    cudaFuncSetAttribute(gemm_tc, cudaFuncAttributeMaxDynamicSharedMemorySize, SM_TOTAL);
    cudaFuncSetAttribute(flash_kernel, cudaFuncAttributeMaxDynamicSharedMemorySize, FL_TOTAL);

    wsplit_dual<<<dim3(96, 32, 2), 256>>>(w_qkv, wq0, DIM, 3 * DIM,
                                          w_o, wo0, DIM, DIM);
    wsplit_dual<<<dim3(128, 32, 2), 256>>>(w1, w10, DIM, MLPD,
                                           w2, w20, MLPD, DIM);

    for (int layer = 0; layer < 4; layer++) {
        const float* xin = (layer == 0) ? x : gx;

        // --- attention ---
        ln_split_kernel<<<RTOK, 256>>>(xin, ln1_g, ln1_b, a0, a1);
        gemm_tc<<<dim3(3 * DIM / 128, RTOK / 128), 256, SM_TOTAL>>>(
            a0, a1, wq0, nullptr, nullptr, nullptr, q0, q1,
            k0, v0, 3 * DIM, DIM, 3);
        flash_kernel<<<dim3(8, NBH), 256, FL_TOTAL>>>(
            q0, q1, k0, v0, a0, a1);
        gemm_tc<<<dim3(DIM / 128, RTOK / 128), 256, SM_TOTAL>>>(
            a0, a1, wo0, b_o, xin, gx, nullptr, nullptr,
            nullptr, nullptr, DIM, DIM, 1);

        // --- MLP ---
        ln_split_kernel<<<RTOK, 256>>>(gx, ln2_g, ln2_b, a0, a1);
        gemm_tc<<<dim3(MLPD / 128, RTOK / 128), 256, SM_TOTAL>>>(
            a0, a1, w10, b1, nullptr, nullptr, h0, h1,
            nullptr, nullptr, MLPD, DIM, 2);
        float* outp = (layer == 3) ? (float*)d_out : gx;
        gemm_tc<<<dim3(DIM / 128, RTOK / 128), 256, SM_TOTAL>>>(
            h0, h1, w20, b2, gx, outp, nullptr, nullptr,
            nullptr, nullptr, DIM, MLPD, 1);
    }
}

// round 14
// speedup vs baseline: 2.0387x; 1.4465x over previous
#include <cuda_runtime.h>
#include <cuda_fp16.h>
#include <math.h>
#include <stdint.h>

#define RTOK 2048
#define DIM  1024
#define NH   16
#define HDIM 64
#define MLPD 4096
#define NBH  32
#define SEQ  1024

// ------------------------- scratch (device globals) -------------------------
__device__ float g_x[RTOK * DIM];
__device__ __align__(128) __half g_a0[RTOK * DIM];
__device__ __align__(128) __half g_h0[RTOK * MLPD];
__device__ __align__(128) __half g_q0[RTOK * DIM], g_q1[RTOK * DIM];
__device__ __align__(128) __half g_k0[RTOK * DIM];
__device__ __align__(128) __half g_v0[RTOK * DIM];
__device__ __align__(128) __half g_wq0[3*DIM*DIM];
__device__ __align__(128) __half g_wo0[DIM*DIM];
__device__ __align__(128) __half g_w10[MLPD*DIM];
__device__ __align__(128) __half g_w20[DIM*MLPD];

// ------------------------- helpers -------------------------
__device__ __forceinline__ uint32_t smem_u32(const void* p) {
    uint32_t a;
    asm("{ .reg .u64 t; cvta.to.shared.u64 t, %1; cvt.u32.u64 %0, t; }" : "=r"(a) : "l"(p));
    return a;
}
__device__ __forceinline__ uint32_t sw128(uint32_t off) { return off ^ ((off >> 3) & 0x70); }

__device__ __forceinline__ size_t packed_off(int row, int col, int K) {
    int rb = row >> 7, kc = col >> 6;
    uint32_t off = ((uint32_t)(row & 127) << 7) | ((uint32_t)(col & 63) << 1);
    off = off ^ ((off >> 3) & 0x70);
    return ((size_t)(rb * (K >> 6) + kc) << 14) + off;
}

__device__ __forceinline__ void mbar_init(uint32_t a, uint32_t cnt) {
    asm volatile("mbarrier.init.shared.b64 [%0], %1;" :: "r"(a), "r"(cnt) : "memory");
}
__device__ __forceinline__ void mbar_expect_tx(uint32_t a, uint32_t bytes) {
    asm volatile("mbarrier.arrive.expect_tx.shared.b64 _, [%0], %1;" :: "r"(a), "r"(bytes) : "memory");
}
__device__ __forceinline__ void mbar_wait(uint32_t a, uint32_t parity) {
    asm volatile(
        "{\n\t.reg .pred P1;\n\t"
        "LAB_WAIT_%=:\n\t"
        "mbarrier.try_wait.parity.acquire.cta.shared::cta.b64 P1, [%0], %1, 0x989680;\n\t"
        "@P1 bra.uni LAB_DONE_%=;\n\t"
        "bra.uni LAB_WAIT_%=;\n\t"
        "LAB_DONE_%=:\n\t}"
        :: "r"(a), "r"(parity) : "memory");
}
__device__ __forceinline__ void bulk_g2s(uint32_t dst, const void* src, uint32_t bytes, uint32_t mbar) {
    asm volatile(
        "cp.async.bulk.shared::cta.global.mbarrier::complete_tx::bytes [%0], [%1], %2, [%3];"
        :: "r"(dst), "l"(src), "r"(bytes), "r"(mbar) : "memory");
}
__device__ __forceinline__ void ldsm4(uint32_t* r, uint32_t addr) {
    asm volatile("ldmatrix.sync.aligned.m8n8.x4.shared.b16 {%0,%1,%2,%3}, [%4];"
                 : "=r"(r[0]), "=r"(r[1]), "=r"(r[2]), "=r"(r[3]) : "r"(addr));
}
__device__ __forceinline__ void ldsm4t(uint32_t* r, uint32_t addr) {
    asm volatile("ldmatrix.sync.aligned.m8n8.x4.trans.shared.b16 {%0,%1,%2,%3}, [%4];"
                 : "=r"(r[0]), "=r"(r[1]), "=r"(r[2]), "=r"(r[3]) : "r"(addr));
}
__device__ __forceinline__ void mma16816(float* c, const uint32_t* a, const uint32_t* b) {
    asm volatile(
        "mma.sync.aligned.m16n8k16.row.col.f32.f16.f16.f32 "
        "{%0,%1,%2,%3}, {%4,%5,%6,%7}, {%8,%9}, {%0,%1,%2,%3};"
        : "+f"(c[0]), "+f"(c[1]), "+f"(c[2]), "+f"(c[3])
        : "r"(a[0]), "r"(a[1]), "r"(a[2]), "r"(a[3]), "r"(b[0]), "r"(b[1]));
}
__device__ __forceinline__ float ex2(float x) {
    float y; asm("ex2.approx.f32 %0, %1;" : "=f"(y) : "f"(x)); return y;
}
__device__ __forceinline__ uint32_t hpack_hi(float x, float y) {
    __half2 t(__float2half_rn(x), __float2half_rn(y));
    return *reinterpret_cast<uint32_t*>(&t);
}
__device__ __forceinline__ uint32_t hpack_lo(float x, float y) {
    float hx = __half2float(__float2half_rn(x));
    float hy = __half2float(__float2half_rn(y));
    __half2 t(__float2half_rn(x - hx), __float2half_rn(y - hy));
    return *reinterpret_cast<uint32_t*>(&t);
}

#define TILE_BYTES  16384
#define G_STAGE     32768
#define SM_TILES    1024
#define NSTAGE      3
#define SM_TOTAL    (SM_TILES + NSTAGE * G_STAGE)

// ------------------- fp16 plain tensor GEMM 128x128 (split-1) -------------------
// C = A[M,K] @ B^T, both plain fp16 packed.
// epi: 0 fp32; 1 +bias+Res fp32; 2 +bias GELU -> packed fp16 hi; 3 QKV per-head (Q hi/lo, K hi, V hi)
__global__ __launch_bounds__(256, 1) void gemm_tc(
    const char* __restrict__ A, const char* __restrict__ B,
    const float* __restrict__ bias, const float* __restrict__ Res,
    float* __restrict__ Cf, char* __restrict__ C0, char* __restrict__ C1,
    char* __restrict__ K0o, char* __restrict__ V0o,
    int N, int K, int epi)
{
    extern __shared__ char smem[];
    uint32_t sb = smem_u32(smem);
    int tid = threadIdx.x, wid = tid >> 5, lane = tid & 31;
    int m0 = blockIdx.y * 128, n0 = blockIdx.x * 128;
    int warp_m = (wid >> 1) * 32, warp_n = (wid & 1) * 64;
    const int NC = K >> 6;

    if (tid == 0) { mbar_init(sb, 1); mbar_init(sb + 8, 1); mbar_init(sb + 16, 1); }
    __syncthreads();

    size_t abase = ((size_t)((m0 >> 7) * NC)) << 14;
    size_t bbase = ((size_t)((n0 >> 7) * NC)) << 14;

    auto load_chunk = [&](int c, int s) {
        uint32_t mb = sb + s * 8;
        uint32_t dst = sb + SM_TILES + s * G_STAGE;
        size_t go = (size_t)c << 14;
        mbar_expect_tx(mb, G_STAGE);
        bulk_g2s(dst,              A + abase + go, TILE_BYTES, mb);
        bulk_g2s(dst + TILE_BYTES, B + bbase + go, TILE_BYTES, mb);
    };

    if (tid == 0) { load_chunk(0, 0); load_chunk(1, 1); }

    float acc[2][8][4];
#pragma unroll
    for (int i = 0; i < 2; i++)
#pragma unroll
        for (int j = 0; j < 8; j++)
#pragma unroll
            for (int q = 0; q < 4; q++) acc[i][j][q] = 0.f;

    int a_row = warp_m + (lane & 15);
    int a_ks  = (lane >> 4) << 4;
    int b_nr  = warp_n + ((lane >> 4) << 3) + (lane & 7);
    int b_ks  = ((lane >> 3) & 1) << 4;

    int stage = 0, phase = 0;
    for (int c = 0; c < NC; c++) {
        mbar_wait(sb + stage * 8, phase);
        if (tid == 0 && c + 2 < NC) {
            int s2 = stage + 2; if (s2 >= NSTAGE) s2 -= NSTAGE;
            load_chunk(c + 2, s2);
        }

        uint32_t base = sb + SM_TILES + stage * G_STAGE;
#pragma unroll
        for (int ks = 0; ks < 4; ks++) {
            uint32_t aA[2][4];
#pragma unroll
            for (int mi = 0; mi < 2; mi++) {
                uint32_t off = sw128((uint32_t)(a_row + mi * 16) * 128 + ks * 32 + a_ks);
                ldsm4(aA[mi], base + off);
            }
#pragma unroll
            for (int nj = 0; nj < 4; nj++) {
                uint32_t boff = sw128((uint32_t)(b_nr + nj * 16) * 128 + ks * 32 + b_ks);
                uint32_t bfr[4];
                ldsm4(bfr, base + TILE_BYTES + boff);
#pragma unroll
                for (int mi = 0; mi < 2; mi++)
#pragma unroll
                    for (int nf = 0; nf < 2; nf++)
                        mma16816(acc[mi][nj * 2 + nf], aA[mi], bfr + 2 * nf);
            }
        }
        __syncthreads();
        if (++stage == NSTAGE) { stage = 0; phase ^= 1; }
    }

    int mrow = m0 + warp_m + (lane >> 2);
    int ncol = n0 + warp_n + (lane & 3) * 2;
#pragma unroll
    for (int mi = 0; mi < 2; mi++) {
#pragma unroll
        for (int nj = 0; nj < 8; nj++) {
#pragma unroll
            for (int h = 0; h < 2; h++) {
                int m = mrow + mi * 16 + h * 8;
                int n = ncol + nj * 8;
                float v0 = acc[mi][nj][2 * h];
                float v1 = acc[mi][nj][2 * h + 1];
                if (epi == 0) {
                    *reinterpret_cast<float2*>(Cf + (size_t)m * N + n) = make_float2(v0, v1);
                } else if (epi == 1) {
                    size_t off = (size_t)m * N + n;
                    float2 r = *reinterpret_cast<const float2*>(Res + off);
                    *reinterpret_cast<float2*>(Cf + off) =
                        make_float2(v0 + bias[n] + r.x, v1 + bias[n + 1] + r.y);
                } else if (epi == 2) {
                    float t0 = v0 + bias[n],     t1 = v1 + bias[n + 1];
                    float g0 = 0.5f * t0 * (1.0f + erff(t0 * 0.70710678118654752f));
                    float g1 = 0.5f * t1 * (1.0f + erff(t1 * 0.70710678118654752f));
                    size_t po = packed_off(m, n, N);
                    *reinterpret_cast<uint32_t*>(C0 + po) = hpack_hi(g0, g1);
                } else {
                    int sel = n >> 10;
                    int hh  = (n >> 6) & 15;
                    int d   = n & 63;
                    int bb  = m >> 10;
                    int qq  = m & 1023;
                    int blk = ((bb * 16 + hh) * 8) + (qq >> 7);
                    uint32_t off = (uint32_t)(qq & 127) * 128 + d * 2;
                    off ^= (off >> 3) & 0x70;
                    size_t po = ((size_t)blk << 14) + off;
                    if (sel == 0) {
                        *reinterpret_cast<uint32_t*>(C0 + po) = hpack_hi(v0, v1);
                        *reinterpret_cast<uint32_t*>(C1 + po) = hpack_lo(v0, v1);
                    } else if (sel == 1) {
                        *reinterpret_cast<uint32_t*>(K0o + po) = hpack_hi(v0, v1);
                    } else {
                        *reinterpret_cast<uint32_t*>(V0o + po) = hpack_hi(v0, v1);
                    }
                }
            }
        }
    }
}

// ------------------------- flash attention (R10 structure: Q split-2, P split-2) -------
#define FL_STAGE 32768
#define FL_SMQ   1024
#define FL_SMKV  (1024 + 32768)
#define FL_TOTAL (1024 + 32768 + 3 * 32768)

__global__ __launch_bounds__(256, 1) void flash_kernel(
    const char* __restrict__ Q0, const char* __restrict__ Q1,
    const char* __restrict__ K0, const char* __restrict__ V0,
    char* __restrict__ O0)
{
    extern __shared__ char smem[];
    uint32_t sb = smem_u32(smem);
    int tid = threadIdx.x, wid = tid >> 5, lane = tid & 31;
    int qb = blockIdx.x, bh = blockIdx.y;
    const float SCALE_LOG2E = 0.03125f * 1.44269504088896341f;

    if (tid == 0) {
        mbar_init(sb, 1); mbar_init(sb + 8, 1); mbar_init(sb + 16, 1); mbar_init(sb + 24, 1);
    }
    __syncthreads();

    auto load_chunk = [&](int j, int s) {
        uint32_t mb = sb + s * 8;
        uint32_t dst = sb + FL_SMKV + s * FL_STAGE;
        size_t go = ((size_t)(bh * 8 + j)) << 14;
        mbar_expect_tx(mb, FL_STAGE);
        bulk_g2s(dst,         K0 + go, TILE_BYTES, mb);
        bulk_g2s(dst + 16384, V0 + go, TILE_BYTES, mb);
    };

    if (tid == 0) {
        size_t qo = ((size_t)(bh * 8 + qb)) << 14;
        mbar_expect_tx(sb + 24, 32768);
        bulk_g2s(sb + FL_SMQ,         Q0 + qo, TILE_BYTES, sb + 24);
        bulk_g2s(sb + FL_SMQ + 16384, Q1 + qo, TILE_BYTES, sb + 24);
        load_chunk(0, 0);
        load_chunk(1, 1);
    }

    mbar_wait(sb + 24, 0);
    uint32_t aQ0[4][4], aQ1[4][4];
    {
        int a_row = wid * 16 + (lane & 15);
        int a_ks  = (lane >> 4) << 4;
#pragma unroll
        for (int ks = 0; ks < 4; ks++) {
            uint32_t off = sw128((uint32_t)a_row * 128 + ks * 32 + a_ks);
            ldsm4(aQ0[ks], sb + FL_SMQ + off);
            ldsm4(aQ1[ks], sb + FL_SMQ + 16384 + off);
        }
    }

    float acc_o[8][4];
#pragma unroll
    for (int i = 0; i < 8; i++)
#pragma unroll
        for (int q = 0; q < 4; q++) acc_o[i][q] = 0.f;
    float m0 = -1e30f, m1 = -1e30f, l0 = 0.f, l1 = 0.f;

    int b_nr = (lane >> 4) * 8 + (lane & 7);
    int b_ks = ((lane >> 3) & 1) << 4;
    int v_row = lane & 15;
    int v_cs  = (lane >> 4) << 4;

    int stage = 0, phase = 0;
    for (int j = 0; j < 8; j++) {
        mbar_wait(sb + stage * 8, phase);
        if (tid == 0 && j + 2 < 8) {
            int s2 = stage + 2; if (s2 >= NSTAGE) s2 -= NSTAGE;
            load_chunk(j + 2, s2);
        }

        uint32_t kb = sb + FL_SMKV + stage * FL_STAGE;
        uint32_t vb = kb + 16384;

        float p[16][4];
#pragma unroll
        for (int i = 0; i < 16; i++)
#pragma unroll
            for (int q = 0; q < 4; q++) p[i][q] = 0.f;

#pragma unroll
        for (int nt = 0; nt < 8; nt++) {
#pragma unroll
            for (int ks = 0; ks < 4; ks++) {
                uint32_t off = sw128((uint32_t)(nt * 16 + b_nr) * 128 + ks * 32 + b_ks);
                uint32_t kfr[4];
                ldsm4(kfr, kb + off);
#pragma unroll
                for (int nf = 0; nf < 2; nf++)
                    mma16816(p[nt * 2 + nf], aQ0[ks], kfr + 2 * nf);
#pragma unroll
                for (int nf = 0; nf < 2; nf++)
                    mma16816(p[nt * 2 + nf], aQ1[ks], kfr + 2 * nf);
            }
        }

        float cm0 = -1e30f, cm1 = -1e30f;
#pragma unroll
        for (int i = 0; i < 16; i++) {
            cm0 = fmaxf(cm0, fmaxf(p[i][0], p[i][1]));
            cm1 = fmaxf(cm1, fmaxf(p[i][2], p[i][3]));
        }
        cm0 = fmaxf(cm0, __shfl_xor_sync(0xffffffffu, cm0, 1));
        cm0 = fmaxf(cm0, __shfl_xor_sync(0xffffffffu, cm0, 2));
        cm1 = fmaxf(cm1, __shfl_xor_sync(0xffffffffu, cm1, 1));
        cm1 = fmaxf(cm1, __shfl_xor_sync(0xffffffffu, cm1, 2));
        float mn0 = fmaxf(m0, cm0 * SCALE_LOG2E);
        float mn1 = fmaxf(m1, cm1 * SCALE_LOG2E);
        float al0 = ex2(m0 - mn0), al1 = ex2(m1 - mn1);
        m0 = mn0; m1 = mn1;

        float sum0 = 0.f, sum1 = 0.f;
#pragma unroll
        for (int i = 0; i < 16; i++) {
            p[i][0] = ex2(p[i][0] * SCALE_LOG2E - m0); sum0 += p[i][0];
            p[i][1] = ex2(p[i][1] * SCALE_LOG2E - m0); sum0 += p[i][1];
            p[i][2] = ex2(p[i][2] * SCALE_LOG2E - m1); sum1 += p[i][2];
            p[i][3] = ex2(p[i][3] * SCALE_LOG2E - m1); sum1 += p[i][3];
        }
        sum0 += __shfl_xor_sync(0xffffffffu, sum0, 1);
        sum0 += __shfl_xor_sync(0xffffffffu, sum0, 2);
        sum1 += __shfl_xor_sync(0xffffffffu, sum1, 1);
        sum1 += __shfl_xor_sync(0xffffffffu, sum1, 2);
        l0 = al0 * l0 + sum0;
        l1 = al1 * l1 + sum1;

#pragma unroll
        for (int i = 0; i < 8; i++) {
            acc_o[i][0] *= al0; acc_o[i][1] *= al0;
            acc_o[i][2] *= al1; acc_o[i][3] *= al1;
        }

#pragma unroll
        for (int kk = 0; kk < 8; kk++) {
            uint32_t phi[4], plo[4];
            phi[0] = hpack_hi(p[kk*2][0],   p[kk*2][1]);
            plo[0] = hpack_lo(p[kk*2][0],   p[kk*2][1]);
            phi[1] = hpack_hi(p[kk*2][2],   p[kk*2][3]);
            plo[1] = hpack_lo(p[kk*2][2],   p[kk*2][3]);
            phi[2] = hpack_hi(p[kk*2+1][0], p[kk*2+1][1]);
            plo[2] = hpack_lo(p[kk*2+1][0], p[kk*2+1][1]);
            phi[3] = hpack_hi(p[kk*2+1][2], p[kk*2+1][3]);
            plo[3] = hpack_lo(p[kk*2+1][2], p[kk*2+1][3]);
#pragma unroll
            for (int vt = 0; vt < 4; vt++) {
                uint32_t off = sw128((uint32_t)(kk * 16 + v_row) * 128 + vt * 32 + v_cs);
                uint32_t vfr[4];
                ldsm4t(vfr, vb + off);
#pragma unroll
                for (int nf = 0; nf < 2; nf++)
                    mma16816(acc_o[vt * 2 + nf], phi, vfr + 2 * nf);
#pragma unroll
                for (int nf = 0; nf < 2; nf++)
                    mma16816(acc_o[vt * 2 + nf], plo, vfr + 2 * nf);
            }
        }
        __syncthreads();
        if (++stage == NSTAGE) { stage = 0; phase ^= 1; }
    }

    float inv0 = 1.f / l0, inv1 = 1.f / l1;
    int bb = bh >> 4, hh = bh & 15;
    int grow = bb * SEQ + qb * 128 + wid * 16 + (lane >> 2);
#pragma unroll
    for (int f = 0; f < 8; f++) {
        int col = hh * 64 + f * 8 + (lane & 3) * 2;
        float x0 = acc_o[f][0] * inv0, y0 = acc_o[f][1] * inv0;
        float x1 = acc_o[f][2] * inv1, y1 = acc_o[f][3] * inv1;
        size_t po0 = packed_off(grow, col, DIM);
        size_t po1 = packed_off(grow + 8, col, DIM);
        *reinterpret_cast<uint32_t*>(O0 + po0) = hpack_hi(x0, y0);
        *reinterpret_cast<uint32_t*>(O0 + po1) = hpack_hi(x1, y1);
    }
}

// ------------------------- reductions -------------------------
__device__ __forceinline__ float warp_sum(float v) {
#pragma unroll
    for (int o = 16; o; o >>= 1) v += __shfl_xor_sync(0xffffffffu, v, o);
    return v;
}

// ------------------------- layernorm -> packed fp16 (hi only) -------------------------
__global__ __launch_bounds__(256) void ln_split_kernel(
    const float* __restrict__ X, const float* __restrict__ G,
    const float* __restrict__ B, char* __restrict__ Y0)
{
    __shared__ float red[8];
    int row = blockIdx.x;
    int tid = threadIdx.x;
    int lane = tid & 31, wid = tid >> 5;

    float4 v = reinterpret_cast<const float4*>(X + (size_t)row * DIM)[tid];
    float s = v.x + v.y + v.z + v.w;
    s = warp_sum(s);
    if (lane == 0) red[wid] = s;
    __syncthreads();
    if (wid == 0) {
        float t = (lane < 8) ? red[lane] : 0.f;
        t = warp_sum(t);
        if (lane == 0) red[0] = t;
    }
    __syncthreads();
    float mu = red[0] * (1.0f / DIM);
    __syncthreads();

    float4 d;
    d.x = v.x - mu; d.y = v.y - mu; d.z = v.z - mu; d.w = v.w - mu;
    float sq = d.x*d.x + d.y*d.y + d.z*d.z + d.w*d.w;
    sq = warp_sum(sq);
    if (lane == 0) red[wid] = sq;
    __syncthreads();
    if (wid == 0) {
        float t = (lane < 8) ? red[lane] : 0.f;
        t = warp_sum(t);
        if (lane == 0) red[0] = t;
    }
    __syncthreads();
    float rs = rsqrtf(red[0] * (1.0f / DIM) + 1e-5f);

    float4 g4 = reinterpret_cast<const float4*>(G)[tid];
    float4 b4 = reinterpret_cast<const float4*>(B)[tid];
    float y[4];
    y[0] = d.x * rs * g4.x + b4.x;
    y[1] = d.y * rs * g4.y + b4.y;
    y[2] = d.z * rs * g4.z + b4.z;
    y[3] = d.w * rs * g4.w + b4.w;

    size_t po = packed_off(row, tid * 4, DIM);
    *reinterpret_cast<uint2*>(Y0 + po) = make_uint2(hpack_hi(y[0], y[1]), hpack_hi(y[2], y[3]));
}

// ------------------------- weight transpose -> plain fp16 packed ----------------------
__global__ __launch_bounds__(256) void wsplit_dual(
    const float* __restrict__ Wa, char* __restrict__ Ta, int Ka, int Na,
    const float* __restrict__ Wb, char* __restrict__ Tb, int Kb, int Nb)
{
    const float* W; char* T; int K, N, n0, k0;
    if (blockIdx.z == 0) {
        W = Wa; T = Ta; K = Ka; N = Na;
        n0 = blockIdx.x * 32; k0 = blockIdx.y * 32;
    } else {
        W = Wb; T = Tb; K = Kb; N = Nb;
        n0 = blockIdx.y * 32; k0 = blockIdx.x * 32;
    }
    if (n0 >= N || k0 >= K) return;

    __shared__ float t[32][33];
    int c = threadIdx.x & 31, r = threadIdx.x >> 5;
#pragma unroll
    for (int rr = 0; rr < 32; rr += 8)
        t[r + rr][c] = W[(size_t)(k0 + r + rr) * N + n0 + c];
    __syncthreads();
    int tx = threadIdx.x & 7;
    int ty = threadIdx.x >> 3;
    int n = n0 + ty, k = k0 + tx * 4;
    float v0 = t[tx*4+0][ty], v1 = t[tx*4+1][ty], v2 = t[tx*4+2][ty], v3 = t[tx*4+3][ty];
    size_t po = packed_off(n, k, K);
    *reinterpret_cast<uint2*>(T + po) = make_uint2(hpack_hi(v0, v1), hpack_hi(v2, v3));
}

// ------------------------- launch -------------------------
extern "C" void kernel_launch(void* const* d_in, const int* in_sizes, int n_in,
                              void* d_out, int out_size)
{
    const float* x     = (const float*)d_in[0];
    const float* ln1_g = (const float*)d_in[1];
    const float* ln1_b = (const float*)d_in[2];
    const float* w_qkv = (const float*)d_in[3];
    const float* w_o   = (const float*)d_in[4];
    const float* b_o   = (const float*)d_in[5];
    const float* ln2_g = (const float*)d_in[6];
    const float* ln2_b = (const float*)d_in[7];
    const float* w1    = (const float*)d_in[8];
    const float* b1    = (const float*)d_in[9];
    const float* w2    = (const float*)d_in[10];
    const float* b2    = (const float*)d_in[11];

    float *gx;
    char *a0, *h0, *q0, *q1, *k0, *v0;
    char *wq0, *wo0, *w10, *w20;
    cudaGetSymbolAddress((void**)&gx,  g_x);
    cudaGetSymbolAddress((void**)&a0,  g_a0);
    cudaGetSymbolAddress((void**)&h0,  g_h0);
    cudaGetSymbolAddress((void**)&q0,  g_q0);
    cudaGetSymbolAddress((void**)&q1,  g_q1);
    cudaGetSymbolAddress((void**)&k0,  g_k0);
    cudaGetSymbolAddress((void**)&v0,  g_v0);
    cudaGetSymbolAddress((void**)&wq0, g_wq0);
    cudaGetSymbolAddress((void**)&wo0, g_wo0);
    cudaGetSymbolAddress((void**)&w10, g_w10);
    cudaGetSymbolAddress((void**)&w20, g_w20);

    cudaFuncSetAttribute(gemm_tc, cudaFuncAttributeMaxDynamicSharedMemorySize, SM_TOTAL);
    cudaFuncSetAttribute(flash_kernel, cudaFuncAttributeMaxDynamicSharedMemorySize, FL_TOTAL);

    wsplit_dual<<<dim3(96, 32, 2), 256>>>(w_qkv, wq0, DIM, 3 * DIM,
                                          w_o, wo0, DIM, DIM);
    wsplit_dual<<<dim3(128, 32, 2), 256>>>(w1, w10, DIM, MLPD,
                                           w2, w20, MLPD, DIM);

    for (int layer = 0; layer < 4; layer++) {
        const float* xin = (layer == 0) ? x : gx;

        // --- attention ---
        ln_split_kernel<<<RTOK, 256>>>(xin, ln1_g, ln1_b, a0);
        gemm_tc<<<dim3(3 * DIM / 128, RTOK / 128), 256, SM_TOTAL>>>(
            a0, wq0, nullptr, nullptr, nullptr, q0, q1,
            k0, v0, 3 * DIM, DIM, 3);
        flash_kernel<<<dim3(8, NBH), 256, FL_TOTAL>>>(
            q0, q1, k0, v0, a0);
        gemm_tc<<<dim3(DIM / 128, RTOK / 128), 256, SM_TOTAL>>>(
            a0, wo0, b_o, xin, gx, nullptr, nullptr,
            nullptr, nullptr, DIM, DIM, 1);

        // --- MLP ---
        ln_split_kernel<<<RTOK, 256>>>(gx, ln2_g, ln2_b, a0);
        gemm_tc<<<dim3(MLPD / 128, RTOK / 128), 256, SM_TOTAL>>>(
            a0, w10, b1, nullptr, nullptr, h0, nullptr,
            nullptr, nullptr, MLPD, DIM, 2);
        float* outp = (layer == 3) ? (float*)d_out : gx;
        gemm_tc<<<dim3(DIM / 128, RTOK / 128), 256, SM_TOTAL>>>(
            h0, w20, b2, gx, outp, nullptr, nullptr,
            nullptr, nullptr, DIM, MLPD, 1);
    }
}

// round 15
// speedup vs baseline: 2.3241x; 1.1400x over previous
#include <cuda_runtime.h>
#include <cuda_fp16.h>
#include <math.h>
#include <stdint.h>

#define RTOK 2048
#define DIM  1024
#define NH   16
#define HDIM 64
#define MLPD 4096
#define NBH  32
#define SEQ  1024

// ------------------------- scratch (device globals) -------------------------
__device__ float g_x[RTOK * DIM];
__device__ __align__(128) __half g_a0[RTOK * DIM];
__device__ __align__(128) __half g_h0[RTOK * MLPD];
__device__ __align__(128) __half g_q0[RTOK * DIM];
__device__ __align__(128) __half g_k0[RTOK * DIM];
__device__ __align__(128) __half g_v0[RTOK * DIM];
__device__ __align__(128) __half g_wq0[3*DIM*DIM];
__device__ __align__(128) __half g_wo0[DIM*DIM];
__device__ __align__(128) __half g_w10[MLPD*DIM];
__device__ __align__(128) __half g_w20[DIM*MLPD];

// ------------------------- helpers -------------------------
__device__ __forceinline__ uint32_t smem_u32(const void* p) {
    uint32_t a;
    asm("{ .reg .u64 t; cvta.to.shared.u64 t, %1; cvt.u32.u64 %0, t; }" : "=r"(a) : "l"(p));
    return a;
}
__device__ __forceinline__ uint32_t sw128(uint32_t off) { return off ^ ((off >> 3) & 0x70); }

__device__ __forceinline__ size_t packed_off(int row, int col, int K) {
    int rb = row >> 7, kc = col >> 6;
    uint32_t off = ((uint32_t)(row & 127) << 7) | ((uint32_t)(col & 63) << 1);
    off = off ^ ((off >> 3) & 0x70);
    return ((size_t)(rb * (K >> 6) + kc) << 14) + off;
}

__device__ __forceinline__ void mbar_init(uint32_t a, uint32_t cnt) {
    asm volatile("mbarrier.init.shared.b64 [%0], %1;" :: "r"(a), "r"(cnt) : "memory");
}
__device__ __forceinline__ void mbar_expect_tx(uint32_t a, uint32_t bytes) {
    asm volatile("mbarrier.arrive.expect_tx.shared.b64 _, [%0], %1;" :: "r"(a), "r"(bytes) : "memory");
}
__device__ __forceinline__ void mbar_wait(uint32_t a, uint32_t parity) {
    asm volatile(
        "{\n\t.reg .pred P1;\n\t"
        "LAB_WAIT_%=:\n\t"
        "mbarrier.try_wait.parity.acquire.cta.shared::cta.b64 P1, [%0], %1, 0x989680;\n\t"
        "@P1 bra.uni LAB_DONE_%=;\n\t"
        "bra.uni LAB_WAIT_%=;\n\t"
        "LAB_DONE_%=:\n\t}"
        :: "r"(a), "r"(parity) : "memory");
}
__device__ __forceinline__ void bulk_g2s(uint32_t dst, const void* src, uint32_t bytes, uint32_t mbar) {
    asm volatile(
        "cp.async.bulk.shared::cta.global.mbarrier::complete_tx::bytes [%0], [%1], %2, [%3];"
        :: "r"(dst), "l"(src), "r"(bytes), "r"(mbar) : "memory");
}
__device__ __forceinline__ void ldsm4(uint32_t* r, uint32_t addr) {
    asm volatile("ldmatrix.sync.aligned.m8n8.x4.shared.b16 {%0,%1,%2,%3}, [%4];"
                 : "=r"(r[0]), "=r"(r[1]), "=r"(r[2]), "=r"(r[3]) : "r"(addr));
}
__device__ __forceinline__ void ldsm4t(uint32_t* r, uint32_t addr) {
    asm volatile("ldmatrix.sync.aligned.m8n8.x4.trans.shared.b16 {%0,%1,%2,%3}, [%4];"
                 : "=r"(r[0]), "=r"(r[1]), "=r"(r[2]), "=r"(r[3]) : "r"(addr));
}
__device__ __forceinline__ void mma16816(float* c, const uint32_t* a, const uint32_t* b) {
    asm volatile(
        "mma.sync.aligned.m16n8k16.row.col.f32.f16.f16.f32 "
        "{%0,%1,%2,%3}, {%4,%5,%6,%7}, {%8,%9}, {%0,%1,%2,%3};"
        : "+f"(c[0]), "+f"(c[1]), "+f"(c[2]), "+f"(c[3])
        : "r"(a[0]), "r"(a[1]), "r"(a[2]), "r"(a[3]), "r"(b[0]), "r"(b[1]));
}
__device__ __forceinline__ float ex2(float x) {
    float y; asm("ex2.approx.f32 %0, %1;" : "=f"(y) : "f"(x)); return y;
}
__device__ __forceinline__ uint32_t hpack_hi(float x, float y) {
    __half2 t(__float2half_rn(x), __float2half_rn(y));
    return *reinterpret_cast<uint32_t*>(&t);
}

#define TILE_BYTES  16384
#define G_STAGE     65536
#define SM_TILES    1024
#define NSTAGE      3
#define SM_TOTAL    (SM_TILES + NSTAGE * G_STAGE)

// ---------------- fp16 GEMM 128x128, K-chunk 128, 3-stage ----------------
// C = A[M,K] @ B^T, plain fp16 packed.
// epi: 0 fp32; 1 +bias+Res fp32; 2 +bias GELU -> fp16; 3 QKV per-head -> fp16
__global__ __launch_bounds__(256, 1) void gemm_tc(
    const char* __restrict__ A, const char* __restrict__ B,
    const float* __restrict__ bias, const float* __restrict__ Res,
    float* __restrict__ Cf, char* __restrict__ C0,
    char* __restrict__ K0o, char* __restrict__ V0o,
    int N, int K, int epi)
{
    extern __shared__ char smem[];
    uint32_t sb = smem_u32(smem);
    int tid = threadIdx.x, wid = tid >> 5, lane = tid & 31;
    int m0 = blockIdx.y * 128, n0 = blockIdx.x * 128;
    int warp_m = (wid >> 1) * 32, warp_n = (wid & 1) * 64;
    const int NC64 = K >> 6;
    const int NC = K >> 7;     // 128-col chunks

    if (tid == 0) { mbar_init(sb, 1); mbar_init(sb + 8, 1); mbar_init(sb + 16, 1); }
    __syncthreads();

    size_t abase = ((size_t)((m0 >> 7) * NC64)) << 14;
    size_t bbase = ((size_t)((n0 >> 7) * NC64)) << 14;

    auto load_chunk = [&](int c, int s) {
        uint32_t mb = sb + s * 8;
        uint32_t dst = sb + SM_TILES + s * G_STAGE;
        size_t go = (size_t)c << 15;             // two 16KB blocks per chunk
        mbar_expect_tx(mb, G_STAGE);
        bulk_g2s(dst,         A + abase + go, 32768, mb);
        bulk_g2s(dst + 32768, B + bbase + go, 32768, mb);
    };

    if (tid == 0) { load_chunk(0, 0); load_chunk(1, 1); }

    float acc[2][8][4];
#pragma unroll
    for (int i = 0; i < 2; i++)
#pragma unroll
        for (int j = 0; j < 8; j++)
#pragma unroll
            for (int q = 0; q < 4; q++) acc[i][j][q] = 0.f;

    int a_row = warp_m + (lane & 15);
    int a_ks  = (lane >> 4) << 4;
    int b_nr  = warp_n + ((lane >> 4) << 3) + (lane & 7);
    int b_ks  = ((lane >> 3) & 1) << 4;

    int stage = 0, phase = 0;
    for (int c = 0; c < NC; c++) {
        mbar_wait(sb + stage * 8, phase);
        if (tid == 0 && c + 2 < NC) {
            int s2 = stage + 2; if (s2 >= NSTAGE) s2 -= NSTAGE;
            load_chunk(c + 2, s2);
        }

        uint32_t base = sb + SM_TILES + stage * G_STAGE;
#pragma unroll
        for (int ks = 0; ks < 8; ks++) {
            uint32_t asub = (uint32_t)(ks >> 2) * TILE_BYTES;
            int ks2 = ks & 3;
            uint32_t aA[2][4];
#pragma unroll
            for (int mi = 0; mi < 2; mi++) {
                uint32_t off = sw128((uint32_t)(a_row + mi * 16) * 128 + ks2 * 32 + a_ks);
                ldsm4(aA[mi], base + asub + off);
            }
#pragma unroll
            for (int nj = 0; nj < 4; nj++) {
                uint32_t boff = sw128((uint32_t)(b_nr + nj * 16) * 128 + ks2 * 32 + b_ks);
                uint32_t bfr[4];
                ldsm4(bfr, base + 32768 + asub + boff);
#pragma unroll
                for (int mi = 0; mi < 2; mi++)
#pragma unroll
                    for (int nf = 0; nf < 2; nf++)
                        mma16816(acc[mi][nj * 2 + nf], aA[mi], bfr + 2 * nf);
            }
        }
        __syncthreads();
        if (++stage == NSTAGE) { stage = 0; phase ^= 1; }
    }

    int mrow = m0 + warp_m + (lane >> 2);
    int ncol = n0 + warp_n + (lane & 3) * 2;
#pragma unroll
    for (int mi = 0; mi < 2; mi++) {
#pragma unroll
        for (int nj = 0; nj < 8; nj++) {
#pragma unroll
            for (int h = 0; h < 2; h++) {
                int m = mrow + mi * 16 + h * 8;
                int n = ncol + nj * 8;
                float v0 = acc[mi][nj][2 * h];
                float v1 = acc[mi][nj][2 * h + 1];
                if (epi == 0) {
                    *reinterpret_cast<float2*>(Cf + (size_t)m * N + n) = make_float2(v0, v1);
                } else if (epi == 1) {
                    size_t off = (size_t)m * N + n;
                    float2 r = *reinterpret_cast<const float2*>(Res + off);
                    *reinterpret_cast<float2*>(Cf + off) =
                        make_float2(v0 + bias[n] + r.x, v1 + bias[n + 1] + r.y);
                } else if (epi == 2) {
                    float t0 = v0 + bias[n],     t1 = v1 + bias[n + 1];
                    float g0 = 0.5f * t0 * (1.0f + erff(t0 * 0.70710678118654752f));
                    float g1 = 0.5f * t1 * (1.0f + erff(t1 * 0.70710678118654752f));
                    size_t po = packed_off(m, n, N);
                    *reinterpret_cast<uint32_t*>(C0 + po) = hpack_hi(g0, g1);
                } else {
                    int sel = n >> 10;
                    int hh  = (n >> 6) & 15;
                    int d   = n & 63;
                    int bb  = m >> 10;
                    int qq  = m & 1023;
                    int blk = ((bb * 16 + hh) * 8) + (qq >> 7);
                    uint32_t off = (uint32_t)(qq & 127) * 128 + d * 2;
                    off ^= (off >> 3) & 0x70;
                    size_t po = ((size_t)blk << 14) + off;
                    char* D = (sel == 0) ? C0 : (sel == 1) ? K0o : V0o;
                    *reinterpret_cast<uint32_t*>(D + po) = hpack_hi(v0, v1);
                }
            }
        }
    }
}

// ------------------------- flash attention (plain fp16) -------------------------
#define FL_STAGE 32768
#define FL_SMQ   1024
#define FL_SMKV  (1024 + 16384)
#define FL_TOTAL (1024 + 16384 + 3 * 32768)

__global__ __launch_bounds__(256, 1) void flash_kernel(
    const char* __restrict__ Q0,
    const char* __restrict__ K0, const char* __restrict__ V0,
    char* __restrict__ O0)
{
    extern __shared__ char smem[];
    uint32_t sb = smem_u32(smem);
    int tid = threadIdx.x, wid = tid >> 5, lane = tid & 31;
    int qb = blockIdx.x, bh = blockIdx.y;
    const float SCALE_LOG2E = 0.03125f * 1.44269504088896341f;

    if (tid == 0) {
        mbar_init(sb, 1); mbar_init(sb + 8, 1); mbar_init(sb + 16, 1); mbar_init(sb + 24, 1);
    }
    __syncthreads();

    auto load_chunk = [&](int j, int s) {
        uint32_t mb = sb + s * 8;
        uint32_t dst = sb + FL_SMKV + s * FL_STAGE;
        size_t go = ((size_t)(bh * 8 + j)) << 14;
        mbar_expect_tx(mb, FL_STAGE);
        bulk_g2s(dst,         K0 + go, TILE_BYTES, mb);
        bulk_g2s(dst + 16384, V0 + go, TILE_BYTES, mb);
    };

    if (tid == 0) {
        size_t qo = ((size_t)(bh * 8 + qb)) << 14;
        mbar_expect_tx(sb + 24, 16384);
        bulk_g2s(sb + FL_SMQ, Q0 + qo, TILE_BYTES, sb + 24);
        load_chunk(0, 0);
        load_chunk(1, 1);
    }

    mbar_wait(sb + 24, 0);
    uint32_t aQ[4][4];
    {
        int a_row = wid * 16 + (lane & 15);
        int a_ks  = (lane >> 4) << 4;
#pragma unroll
        for (int ks = 0; ks < 4; ks++) {
            uint32_t off = sw128((uint32_t)a_row * 128 + ks * 32 + a_ks);
            ldsm4(aQ[ks], sb + FL_SMQ + off);
        }
    }

    float acc_o[8][4];
#pragma unroll
    for (int i = 0; i < 8; i++)
#pragma unroll
        for (int q = 0; q < 4; q++) acc_o[i][q] = 0.f;
    float m0 = -1e30f, m1 = -1e30f, l0 = 0.f, l1 = 0.f;

    int b_nr = (lane >> 4) * 8 + (lane & 7);
    int b_ks = ((lane >> 3) & 1) << 4;
    int v_row = lane & 15;
    int v_cs  = (lane >> 4) << 4;

    int stage = 0, phase = 0;
    for (int j = 0; j < 8; j++) {
        mbar_wait(sb + stage * 8, phase);
        if (tid == 0 && j + 2 < 8) {
            int s2 = stage + 2; if (s2 >= NSTAGE) s2 -= NSTAGE;
            load_chunk(j + 2, s2);
        }

        uint32_t kb = sb + FL_SMKV + stage * FL_STAGE;
        uint32_t vb = kb + 16384;

        float p[16][4];
#pragma unroll
        for (int i = 0; i < 16; i++)
#pragma unroll
            for (int q = 0; q < 4; q++) p[i][q] = 0.f;

#pragma unroll
        for (int nt = 0; nt < 8; nt++) {
#pragma unroll
            for (int ks = 0; ks < 4; ks++) {
                uint32_t off = sw128((uint32_t)(nt * 16 + b_nr) * 128 + ks * 32 + b_ks);
                uint32_t kfr[4];
                ldsm4(kfr, kb + off);
#pragma unroll
                for (int nf = 0; nf < 2; nf++)
                    mma16816(p[nt * 2 + nf], aQ[ks], kfr + 2 * nf);
            }
        }

        float cm0 = -1e30f, cm1 = -1e30f;
#pragma unroll
        for (int i = 0; i < 16; i++) {
            cm0 = fmaxf(cm0, fmaxf(p[i][0], p[i][1]));
            cm1 = fmaxf(cm1, fmaxf(p[i][2], p[i][3]));
        }
        cm0 = fmaxf(cm0, __shfl_xor_sync(0xffffffffu, cm0, 1));
        cm0 = fmaxf(cm0, __shfl_xor_sync(0xffffffffu, cm0, 2));
        cm1 = fmaxf(cm1, __shfl_xor_sync(0xffffffffu, cm1, 1));
        cm1 = fmaxf(cm1, __shfl_xor_sync(0xffffffffu, cm1, 2));
        float mn0 = fmaxf(m0, cm0 * SCALE_LOG2E);
        float mn1 = fmaxf(m1, cm1 * SCALE_LOG2E);
        float al0 = ex2(m0 - mn0), al1 = ex2(m1 - mn1);
        m0 = mn0; m1 = mn1;

        float sum0 = 0.f, sum1 = 0.f;
#pragma unroll
        for (int i = 0; i < 16; i++) {
            p[i][0] = ex2(p[i][0] * SCALE_LOG2E - m0); sum0 += p[i][0];
            p[i][1] = ex2(p[i][1] * SCALE_LOG2E - m0); sum0 += p[i][1];
            p[i][2] = ex2(p[i][2] * SCALE_LOG2E - m1); sum1 += p[i][2];
            p[i][3] = ex2(p[i][3] * SCALE_LOG2E - m1); sum1 += p[i][3];
        }
        sum0 += __shfl_xor_sync(0xffffffffu, sum0, 1);
        sum0 += __shfl_xor_sync(0xffffffffu, sum0, 2);
        sum1 += __shfl_xor_sync(0xffffffffu, sum1, 1);
        sum1 += __shfl_xor_sync(0xffffffffu, sum1, 2);
        l0 = al0 * l0 + sum0;
        l1 = al1 * l1 + sum1;

#pragma unroll
        for (int i = 0; i < 8; i++) {
            acc_o[i][0] *= al0; acc_o[i][1] *= al0;
            acc_o[i][2] *= al1; acc_o[i][3] *= al1;
        }

#pragma unroll
        for (int kk = 0; kk < 8; kk++) {
            uint32_t phi[4];
            phi[0] = hpack_hi(p[kk*2][0],   p[kk*2][1]);
            phi[1] = hpack_hi(p[kk*2][2],   p[kk*2][3]);
            phi[2] = hpack_hi(p[kk*2+1][0], p[kk*2+1][1]);
            phi[3] = hpack_hi(p[kk*2+1][2], p[kk*2+1][3]);
#pragma unroll
            for (int vt = 0; vt < 4; vt++) {
                uint32_t off = sw128((uint32_t)(kk * 16 + v_row) * 128 + vt * 32 + v_cs);
                uint32_t vfr[4];
                ldsm4t(vfr, vb + off);
#pragma unroll
                for (int nf = 0; nf < 2; nf++)
                    mma16816(acc_o[vt * 2 + nf], phi, vfr + 2 * nf);
            }
        }
        __syncthreads();
        if (++stage == NSTAGE) { stage = 0; phase ^= 1; }
    }

    float inv0 = 1.f / l0, inv1 = 1.f / l1;
    int bb = bh >> 4, hh = bh & 15;
    int grow = bb * SEQ + qb * 128 + wid * 16 + (lane >> 2);
#pragma unroll
    for (int f = 0; f < 8; f++) {
        int col = hh * 64 + f * 8 + (lane & 3) * 2;
        float x0 = acc_o[f][0] * inv0, y0 = acc_o[f][1] * inv0;
        float x1 = acc_o[f][2] * inv1, y1 = acc_o[f][3] * inv1;
        size_t po0 = packed_off(grow, col, DIM);
        size_t po1 = packed_off(grow + 8, col, DIM);
        *reinterpret_cast<uint32_t*>(O0 + po0) = hpack_hi(x0, y0);
        *reinterpret_cast<uint32_t*>(O0 + po1) = hpack_hi(x1, y1);
    }
}

// ------------------------- reductions -------------------------
__device__ __forceinline__ float warp_sum(float v) {
#pragma unroll
    for (int o = 16; o; o >>= 1) v += __shfl_xor_sync(0xffffffffu, v, o);
    return v;
}

// ------------------------- layernorm -> packed fp16 -------------------------
__global__ __launch_bounds__(256) void ln_split_kernel(
    const float* __restrict__ X, const float* __restrict__ G,
    const float* __restrict__ B, char* __restrict__ Y0)
{
    __shared__ float red[8];
    int row = blockIdx.x;
    int tid = threadIdx.x;
    int lane = tid & 31, wid = tid >> 5;

    float4 v = reinterpret_cast<const float4*>(X + (size_t)row * DIM)[tid];
    float s = v.x + v.y + v.z + v.w;
    s = warp_sum(s);
    if (lane == 0) red[wid] = s;
    __syncthreads();
    if (wid == 0) {
        float t = (lane < 8) ? red[lane] : 0.f;
        t = warp_sum(t);
        if (lane == 0) red[0] = t;
    }
    __syncthreads();
    float mu = red[0] * (1.0f / DIM);
    __syncthreads();

    float4 d;
    d.x = v.x - mu; d.y = v.y - mu; d.z = v.z - mu; d.w = v.w - mu;
    float sq = d.x*d.x + d.y*d.y + d.z*d.z + d.w*d.w;
    sq = warp_sum(sq);
    if (lane == 0) red[wid] = sq;
    __syncthreads();
    if (wid == 0) {
        float t = (lane < 8) ? red[lane] : 0.f;
        t = warp_sum(t);
        if (lane == 0) red[0] = t;
    }
    __syncthreads();
    float rs = rsqrtf(red[0] * (1.0f / DIM) + 1e-5f);

    float4 g4 = reinterpret_cast<const float4*>(G)[tid];
    float4 b4 = reinterpret_cast<const float4*>(B)[tid];
    float y[4];
    y[0] = d.x * rs * g4.x + b4.x;
    y[1] = d.y * rs * g4.y + b4.y;
    y[2] = d.z * rs * g4.z + b4.z;
    y[3] = d.w * rs * g4.w + b4.w;

    size_t po = packed_off(row, tid * 4, DIM);
    *reinterpret_cast<uint2*>(Y0 + po) = make_uint2(hpack_hi(y[0], y[1]), hpack_hi(y[2], y[3]));
}

// ------------------------- weight transpose -> plain fp16 packed ----------------------
__global__ __launch_bounds__(256) void wsplit_dual(
    const float* __restrict__ Wa, char* __restrict__ Ta, int Ka, int Na,
    const float* __restrict__ Wb, char* __restrict__ Tb, int Kb, int Nb)
{
    const float* W; char* T; int K, N, n0, k0;
    if (blockIdx.z == 0) {
        W = Wa; T = Ta; K = Ka; N = Na;
        n0 = blockIdx.x * 32; k0 = blockIdx.y * 32;
    } else {
        W = Wb; T = Tb; K = Kb; N = Nb;
        n0 = blockIdx.y * 32; k0 = blockIdx.x * 32;
    }
    if (n0 >= N || k0 >= K) return;

    __shared__ float t[32][33];
    int c = threadIdx.x & 31, r = threadIdx.x >> 5;
#pragma unroll
    for (int rr = 0; rr < 32; rr += 8)
        t[r + rr][c] = W[(size_t)(k0 + r + rr) * N + n0 + c];
    __syncthreads();
    int tx = threadIdx.x & 7;
    int ty = threadIdx.x >> 3;
    int n = n0 + ty, k = k0 + tx * 4;
    float v0 = t[tx*4+0][ty], v1 = t[tx*4+1][ty], v2 = t[tx*4+2][ty], v3 = t[tx*4+3][ty];
    size_t po = packed_off(n, k, K);
    *reinterpret_cast<uint2*>(T + po) = make_uint2(hpack_hi(v0, v1), hpack_hi(v2, v3));
}

// ------------------------- launch -------------------------
extern "C" void kernel_launch(void* const* d_in, const int* in_sizes, int n_in,
                              void* d_out, int out_size)
{
    const float* x     = (const float*)d_in[0];
    const float* ln1_g = (const float*)d_in[1];
    const float* ln1_b = (const float*)d_in[2];
    const float* w_qkv = (const float*)d_in[3];
    const float* w_o   = (const float*)d_in[4];
    const float* b_o   = (const float*)d_in[5];
    const float* ln2_g = (const float*)d_in[6];
    const float* ln2_b = (const float*)d_in[7];
    const float* w1    = (const float*)d_in[8];
    const float* b1    = (const float*)d_in[9];
    const float* w2    = (const float*)d_in[10];
    const float* b2    = (const float*)d_in[11];

    float *gx;
    char *a0, *h0, *q0, *k0, *v0;
    char *wq0, *wo0, *w10, *w20;
    cudaGetSymbolAddress((void**)&gx,  g_x);
    cudaGetSymbolAddress((void**)&a0,  g_a0);
    cudaGetSymbolAddress((void**)&h0,  g_h0);
    cudaGetSymbolAddress((void**)&q0,  g_q0);
    cudaGetSymbolAddress((void**)&k0,  g_k0);
    cudaGetSymbolAddress((void**)&v0,  g_v0);
    cudaGetSymbolAddress((void**)&wq0, g_wq0);
    cudaGetSymbolAddress((void**)&wo0, g_wo0);
    cudaGetSymbolAddress((void**)&w10, g_w10);
    cudaGetSymbolAddress((void**)&w20, g_w20);

    cudaFuncSetAttribute(gemm_tc, cudaFuncAttributeMaxDynamicSharedMemorySize, SM_TOTAL);
    cudaFuncSetAttribute(flash_kernel, cudaFuncAttributeMaxDynamicSharedMemorySize, FL_TOTAL);

    wsplit_dual<<<dim3(96, 32, 2), 256>>>(w_qkv, wq0, DIM, 3 * DIM,
                                          w_o, wo0, DIM, DIM);
    wsplit_dual<<<dim3(128, 32, 2), 256>>>(w1, w10, DIM, MLPD,
                                           w2, w20, MLPD, DIM);

    for (int layer = 0; layer < 4; layer++) {
        const float* xin = (layer == 0) ? x : gx;

        // --- attention ---
        ln_split_kernel<<<RTOK, 256>>>(xin, ln1_g, ln1_b, a0);
        gemm_tc<<<dim3(3 * DIM / 128, RTOK / 128), 256, SM_TOTAL>>>(
            a0, wq0, nullptr, nullptr, nullptr, q0,
            k0, v0, 3 * DIM, DIM, 3);
        flash_kernel<<<dim3(8, NBH), 256, FL_TOTAL>>>(
            q0, k0, v0, a0);
        gemm_tc<<<dim3(DIM / 128, RTOK / 128), 256, SM_TOTAL>>>(
            a0, wo0, b_o, xin, gx, nullptr,
            nullptr, nullptr, DIM, DIM, 1);

        // --- MLP ---
        ln_split_kernel<<<RTOK, 256>>>(gx, ln2_g, ln2_b, a0);
        gemm_tc<<<dim3(MLPD / 128, RTOK / 128), 256, SM_TOTAL>>>(
            a0, w10, b1, nullptr, nullptr, h0,
            nullptr, nullptr, MLPD, DIM, 2);
        float* outp = (layer == 3) ? (float*)d_out : gx;
        gemm_tc<<<dim3(DIM / 128, RTOK / 128), 256, SM_TOTAL>>>(
            h0, w20, b2, gx, outp, nullptr,
            nullptr, nullptr, DIM, MLPD, 1);
    }
}

// round 16
// speedup vs baseline: 2.3437x; 1.0084x over previous
#include <cuda_runtime.h>
#include <cuda_fp16.h>
#include <math.h>
#include <stdint.h>

#define RTOK 2048
#define DIM  1024
#define NH   16
#define HDIM 64
#define MLPD 4096
#define NBH  32
#define SEQ  1024

// ------------------------- scratch (device globals) -------------------------
__device__ float g_x[RTOK * DIM];
__device__ __align__(128) __half g_a0[RTOK * DIM];
__device__ __align__(128) __half g_h0[RTOK * MLPD];
__device__ __align__(128) __half g_q0[RTOK * DIM];
__device__ __align__(128) __half g_k0[RTOK * DIM];
__device__ __align__(128) __half g_v0[RTOK * DIM];
__device__ __align__(128) __half g_wq0[3*DIM*DIM];
__device__ __align__(128) __half g_wo0[DIM*DIM];
__device__ __align__(128) __half g_w10[MLPD*DIM];
__device__ __align__(128) __half g_w20[DIM*MLPD];

// ------------------------- helpers -------------------------
__device__ __forceinline__ uint32_t smem_u32(const void* p) {
    uint32_t a;
    asm("{ .reg .u64 t; cvta.to.shared.u64 t, %1; cvt.u32.u64 %0, t; }" : "=r"(a) : "l"(p));
    return a;
}
__device__ __forceinline__ uint32_t sw128(uint32_t off) { return off ^ ((off >> 3) & 0x70); }

__device__ __forceinline__ size_t packed_off(int row, int col, int K) {
    int rb = row >> 7, kc = col >> 6;
    uint32_t off = ((uint32_t)(row & 127) << 7) | ((uint32_t)(col & 63) << 1);
    off = off ^ ((off >> 3) & 0x70);
    return ((size_t)(rb * (K >> 6) + kc) << 14) + off;
}

__device__ __forceinline__ void mbar_init(uint32_t a, uint32_t cnt) {
    asm volatile("mbarrier.init.shared.b64 [%0], %1;" :: "r"(a), "r"(cnt) : "memory");
}
__device__ __forceinline__ void mbar_expect_tx(uint32_t a, uint32_t bytes) {
    asm volatile("mbarrier.arrive.expect_tx.shared.b64 _, [%0], %1;" :: "r"(a), "r"(bytes) : "memory");
}
__device__ __forceinline__ void mbar_wait(uint32_t a, uint32_t parity) {
    asm volatile(
        "{\n\t.reg .pred P1;\n\t"
        "LAB_WAIT_%=:\n\t"
        "mbarrier.try_wait.parity.acquire.cta.shared::cta.b64 P1, [%0], %1, 0x989680;\n\t"
        "@P1 bra.uni LAB_DONE_%=;\n\t"
        "bra.uni LAB_WAIT_%=;\n\t"
        "LAB_DONE_%=:\n\t}"
        :: "r"(a), "r"(parity) : "memory");
}
__device__ __forceinline__ void bulk_g2s(uint32_t dst, const void* src, uint32_t bytes, uint32_t mbar) {
    asm volatile(
        "cp.async.bulk.shared::cta.global.mbarrier::complete_tx::bytes [%0], [%1], %2, [%3];"
        :: "r"(dst), "l"(src), "r"(bytes), "r"(mbar) : "memory");
}
__device__ __forceinline__ void ldsm4(uint32_t* r, uint32_t addr) {
    asm volatile("ldmatrix.sync.aligned.m8n8.x4.shared.b16 {%0,%1,%2,%3}, [%4];"
                 : "=r"(r[0]), "=r"(r[1]), "=r"(r[2]), "=r"(r[3]) : "r"(addr));
}
__device__ __forceinline__ void ldsm4t(uint32_t* r, uint32_t addr) {
    asm volatile("ldmatrix.sync.aligned.m8n8.x4.trans.shared.b16 {%0,%1,%2,%3}, [%4];"
                 : "=r"(r[0]), "=r"(r[1]), "=r"(r[2]), "=r"(r[3]) : "r"(addr));
}
__device__ __forceinline__ void mma16816(float* c, const uint32_t* a, const uint32_t* b) {
    asm volatile(
        "mma.sync.aligned.m16n8k16.row.col.f32.f16.f16.f32 "
        "{%0,%1,%2,%3}, {%4,%5,%6,%7}, {%8,%9}, {%0,%1,%2,%3};"
        : "+f"(c[0]), "+f"(c[1]), "+f"(c[2]), "+f"(c[3])
        : "r"(a[0]), "r"(a[1]), "r"(a[2]), "r"(a[3]), "r"(b[0]), "r"(b[1]));
}
__device__ __forceinline__ float ex2(float x) {
    float y; asm("ex2.approx.f32 %0, %1;" : "=f"(y) : "f"(x)); return y;
}
__device__ __forceinline__ uint32_t hpack_hi(float x, float y) {
    __half2 t(__float2half_rn(x), __float2half_rn(y));
    return *reinterpret_cast<uint32_t*>(&t);
}

#define TILE_BYTES  16384
#define G_STAGE     65536
#define SM_TILES    1024
#define NSTAGE      3
#define SM_TOTAL    (SM_TILES + NSTAGE * G_STAGE)

// ---------------- fp16 GEMM 128x128, K-chunk 128, 3-stage, frag ping-pong ----------------
// C = A[M,K] @ B^T, plain fp16 packed.
// epi: 0 fp32; 1 +bias+Res fp32; 2 +bias GELU -> fp16; 3 QKV per-head -> fp16
__global__ __launch_bounds__(256, 1) void gemm_tc(
    const char* __restrict__ A, const char* __restrict__ B,
    const float* __restrict__ bias, const float* __restrict__ Res,
    float* __restrict__ Cf, char* __restrict__ C0,
    char* __restrict__ K0o, char* __restrict__ V0o,
    int N, int K, int epi)
{
    extern __shared__ char smem[];
    uint32_t sb = smem_u32(smem);
    int tid = threadIdx.x, wid = tid >> 5, lane = tid & 31;
    int m0 = blockIdx.y * 128, n0 = blockIdx.x * 128;
    int warp_m = (wid >> 1) * 32, warp_n = (wid & 1) * 64;
    const int NC64 = K >> 6;
    const int NC = K >> 7;

    if (tid == 0) { mbar_init(sb, 1); mbar_init(sb + 8, 1); mbar_init(sb + 16, 1); }
    __syncthreads();

    size_t abase = ((size_t)((m0 >> 7) * NC64)) << 14;
    size_t bbase = ((size_t)((n0 >> 7) * NC64)) << 14;

    auto load_chunk = [&](int c, int s) {
        uint32_t mb = sb + s * 8;
        uint32_t dst = sb + SM_TILES + s * G_STAGE;
        size_t go = (size_t)c << 15;
        mbar_expect_tx(mb, G_STAGE);
        bulk_g2s(dst,         A + abase + go, 32768, mb);
        bulk_g2s(dst + 32768, B + bbase + go, 32768, mb);
    };

    if (tid == 0) { load_chunk(0, 0); load_chunk(1, 1); }

    float acc[2][8][4];
#pragma unroll
    for (int i = 0; i < 2; i++)
#pragma unroll
        for (int j = 0; j < 8; j++)
#pragma unroll
            for (int q = 0; q < 4; q++) acc[i][j][q] = 0.f;

    int a_row = warp_m + (lane & 15);
    int a_ks  = (lane >> 4) << 4;
    int b_nr  = warp_n + ((lane >> 4) << 3) + (lane & 7);
    int b_ks  = ((lane >> 3) & 1) << 4;

    uint32_t aA[2][2][4], bF[2][4][4];

    int stage = 0, phase = 0;
    for (int c = 0; c < NC; c++) {
        mbar_wait(sb + stage * 8, phase);
        if (tid == 0 && c + 2 < NC) {
            int s2 = stage + 2; if (s2 >= NSTAGE) s2 -= NSTAGE;
            load_chunk(c + 2, s2);
        }

        uint32_t base = sb + SM_TILES + stage * G_STAGE;

        // frag loader for a given ks into buffer buf
        auto load_frags = [&](int ks, int buf) {
            uint32_t asub = (uint32_t)(ks >> 2) * TILE_BYTES;
            int ks2 = ks & 3;
#pragma unroll
            for (int mi = 0; mi < 2; mi++) {
                uint32_t off = sw128((uint32_t)(a_row + mi * 16) * 128 + ks2 * 32 + a_ks);
                ldsm4(aA[buf][mi], base + asub + off);
            }
#pragma unroll
            for (int nj = 0; nj < 4; nj++) {
                uint32_t boff = sw128((uint32_t)(b_nr + nj * 16) * 128 + ks2 * 32 + b_ks);
                ldsm4(bF[buf][nj], base + 32768 + asub + boff);
            }
        };

        load_frags(0, 0);
#pragma unroll
        for (int ks = 0; ks < 8; ks++) {
            int cur = ks & 1;
            if (ks < 7) load_frags(ks + 1, cur ^ 1);
#pragma unroll
            for (int nj = 0; nj < 4; nj++)
#pragma unroll
                for (int mi = 0; mi < 2; mi++)
#pragma unroll
                    for (int nf = 0; nf < 2; nf++)
                        mma16816(acc[mi][nj * 2 + nf], aA[cur][mi], bF[cur][nj] + 2 * nf);
        }
        __syncthreads();
        if (++stage == NSTAGE) { stage = 0; phase ^= 1; }
    }

    int mrow = m0 + warp_m + (lane >> 2);
    int ncol = n0 + warp_n + (lane & 3) * 2;
#pragma unroll
    for (int mi = 0; mi < 2; mi++) {
#pragma unroll
        for (int nj = 0; nj < 8; nj++) {
#pragma unroll
            for (int h = 0; h < 2; h++) {
                int m = mrow + mi * 16 + h * 8;
                int n = ncol + nj * 8;
                float v0 = acc[mi][nj][2 * h];
                float v1 = acc[mi][nj][2 * h + 1];
                if (epi == 0) {
                    *reinterpret_cast<float2*>(Cf + (size_t)m * N + n) = make_float2(v0, v1);
                } else if (epi == 1) {
                    size_t off = (size_t)m * N + n;
                    float2 r = *reinterpret_cast<const float2*>(Res + off);
                    *reinterpret_cast<float2*>(Cf + off) =
                        make_float2(v0 + bias[n] + r.x, v1 + bias[n + 1] + r.y);
                } else if (epi == 2) {
                    float t0 = v0 + bias[n],     t1 = v1 + bias[n + 1];
                    float g0 = 0.5f * t0 * (1.0f + erff(t0 * 0.70710678118654752f));
                    float g1 = 0.5f * t1 * (1.0f + erff(t1 * 0.70710678118654752f));
                    size_t po = packed_off(m, n, N);
                    *reinterpret_cast<uint32_t*>(C0 + po) = hpack_hi(g0, g1);
                } else {
                    int sel = n >> 10;
                    int hh  = (n >> 6) & 15;
                    int d   = n & 63;
                    int bb  = m >> 10;
                    int qq  = m & 1023;
                    int blk = ((bb * 16 + hh) * 8) + (qq >> 7);
                    uint32_t off = (uint32_t)(qq & 127) * 128 + d * 2;
                    off ^= (off >> 3) & 0x70;
                    size_t po = ((size_t)blk << 14) + off;
                    char* D = (sel == 0) ? C0 : (sel == 1) ? K0o : V0o;
                    *reinterpret_cast<uint32_t*>(D + po) = hpack_hi(v0, v1);
                }
            }
        }
    }
}

// ------------------------- flash attention (plain fp16, frag ping-pong) ----------------
#define FL_STAGE 32768
#define FL_SMQ   1024
#define FL_SMKV  (1024 + 16384)
#define FL_TOTAL (1024 + 16384 + 3 * 32768)

__global__ __launch_bounds__(256, 1) void flash_kernel(
    const char* __restrict__ Q0,
    const char* __restrict__ K0, const char* __restrict__ V0,
    char* __restrict__ O0)
{
    extern __shared__ char smem[];
    uint32_t sb = smem_u32(smem);
    int tid = threadIdx.x, wid = tid >> 5, lane = tid & 31;
    int qb = blockIdx.x, bh = blockIdx.y;
    const float SCALE_LOG2E = 0.03125f * 1.44269504088896341f;

    if (tid == 0) {
        mbar_init(sb, 1); mbar_init(sb + 8, 1); mbar_init(sb + 16, 1); mbar_init(sb + 24, 1);
    }
    __syncthreads();

    auto load_chunk = [&](int j, int s) {
        uint32_t mb = sb + s * 8;
        uint32_t dst = sb + FL_SMKV + s * FL_STAGE;
        size_t go = ((size_t)(bh * 8 + j)) << 14;
        mbar_expect_tx(mb, FL_STAGE);
        bulk_g2s(dst,         K0 + go, TILE_BYTES, mb);
        bulk_g2s(dst + 16384, V0 + go, TILE_BYTES, mb);
    };

    if (tid == 0) {
        size_t qo = ((size_t)(bh * 8 + qb)) << 14;
        mbar_expect_tx(sb + 24, 16384);
        bulk_g2s(sb + FL_SMQ, Q0 + qo, TILE_BYTES, sb + 24);
        load_chunk(0, 0);
        load_chunk(1, 1);
    }

    mbar_wait(sb + 24, 0);
    uint32_t aQ[4][4];
    {
        int a_row = wid * 16 + (lane & 15);
        int a_ks  = (lane >> 4) << 4;
#pragma unroll
        for (int ks = 0; ks < 4; ks++) {
            uint32_t off = sw128((uint32_t)a_row * 128 + ks * 32 + a_ks);
            ldsm4(aQ[ks], sb + FL_SMQ + off);
        }
    }

    float acc_o[8][4];
#pragma unroll
    for (int i = 0; i < 8; i++)
#pragma unroll
        for (int q = 0; q < 4; q++) acc_o[i][q] = 0.f;
    float m0 = -1e30f, m1 = -1e30f, l0 = 0.f, l1 = 0.f;

    int b_nr = (lane >> 4) * 8 + (lane & 7);
    int b_ks = ((lane >> 3) & 1) << 4;
    int v_row = lane & 15;
    int v_cs  = (lane >> 4) << 4;

    int stage = 0, phase = 0;
    for (int j = 0; j < 8; j++) {
        mbar_wait(sb + stage * 8, phase);
        if (tid == 0 && j + 2 < 8) {
            int s2 = stage + 2; if (s2 >= NSTAGE) s2 -= NSTAGE;
            load_chunk(j + 2, s2);
        }

        uint32_t kb = sb + FL_SMKV + stage * FL_STAGE;
        uint32_t vb = kb + 16384;

        float p[16][4];
#pragma unroll
        for (int i = 0; i < 16; i++)
#pragma unroll
            for (int q = 0; q < 4; q++) p[i][q] = 0.f;

        // ---- QK^T with K-frag ping-pong over flattened (nt, ks) ----
        {
            uint32_t kfr[2][4];
            ldsm4(kfr[0], kb + sw128((uint32_t)b_nr * 128 + b_ks));
#pragma unroll
            for (int it = 0; it < 32; it++) {
                int nt = it >> 2, ks = it & 3;
                int cur = it & 1;
                if (it + 1 < 32) {
                    int nt2 = (it + 1) >> 2, ks2 = (it + 1) & 3;
                    uint32_t off = sw128((uint32_t)(nt2 * 16 + b_nr) * 128 + ks2 * 32 + b_ks);
                    ldsm4(kfr[cur ^ 1], kb + off);
                }
#pragma unroll
                for (int nf = 0; nf < 2; nf++)
                    mma16816(p[nt * 2 + nf], aQ[ks], kfr[cur] + 2 * nf);
            }
        }

        float cm0 = -1e30f, cm1 = -1e30f;
#pragma unroll
        for (int i = 0; i < 16; i++) {
            cm0 = fmaxf(cm0, fmaxf(p[i][0], p[i][1]));
            cm1 = fmaxf(cm1, fmaxf(p[i][2], p[i][3]));
        }
        cm0 = fmaxf(cm0, __shfl_xor_sync(0xffffffffu, cm0, 1));
        cm0 = fmaxf(cm0, __shfl_xor_sync(0xffffffffu, cm0, 2));
        cm1 = fmaxf(cm1, __shfl_xor_sync(0xffffffffu, cm1, 1));
        cm1 = fmaxf(cm1, __shfl_xor_sync(0xffffffffu, cm1, 2));
        float mn0 = fmaxf(m0, cm0 * SCALE_LOG2E);
        float mn1 = fmaxf(m1, cm1 * SCALE_LOG2E);
        float al0 = ex2(m0 - mn0), al1 = ex2(m1 - mn1);
        m0 = mn0; m1 = mn1;

        float sum0 = 0.f, sum1 = 0.f;
#pragma unroll
        for (int i = 0; i < 16; i++) {
            p[i][0] = ex2(p[i][0] * SCALE_LOG2E - m0); sum0 += p[i][0];
            p[i][1] = ex2(p[i][1] * SCALE_LOG2E - m0); sum0 += p[i][1];
            p[i][2] = ex2(p[i][2] * SCALE_LOG2E - m1); sum1 += p[i][2];
            p[i][3] = ex2(p[i][3] * SCALE_LOG2E - m1); sum1 += p[i][3];
        }
        sum0 += __shfl_xor_sync(0xffffffffu, sum0, 1);
        sum0 += __shfl_xor_sync(0xffffffffu, sum0, 2);
        sum1 += __shfl_xor_sync(0xffffffffu, sum1, 1);
        sum1 += __shfl_xor_sync(0xffffffffu, sum1, 2);
        l0 = al0 * l0 + sum0;
        l1 = al1 * l1 + sum1;

#pragma unroll
        for (int i = 0; i < 8; i++) {
            acc_o[i][0] *= al0; acc_o[i][1] *= al0;
            acc_o[i][2] *= al1; acc_o[i][3] *= al1;
        }

        // ---- P@V with V-frag ping-pong over flattened (kk, vt) ----
        {
            uint32_t vfr[2][4];
            ldsm4t(vfr[0], vb + sw128((uint32_t)v_row * 128 + v_cs));
            uint32_t phi[4];
#pragma unroll
            for (int it = 0; it < 32; it++) {
                int kk = it >> 2, vt = it & 3;
                int cur = it & 1;
                if (vt == 0) {
                    phi[0] = hpack_hi(p[kk*2][0],   p[kk*2][1]);
                    phi[1] = hpack_hi(p[kk*2][2],   p[kk*2][3]);
                    phi[2] = hpack_hi(p[kk*2+1][0], p[kk*2+1][1]);
                    phi[3] = hpack_hi(p[kk*2+1][2], p[kk*2+1][3]);
                }
                if (it + 1 < 32) {
                    int kk2 = (it + 1) >> 2, vt2 = (it + 1) & 3;
                    uint32_t off = sw128((uint32_t)(kk2 * 16 + v_row) * 128 + vt2 * 32 + v_cs);
                    ldsm4t(vfr[cur ^ 1], vb + off);
                }
#pragma unroll
                for (int nf = 0; nf < 2; nf++)
                    mma16816(acc_o[vt * 2 + nf], phi, vfr[cur] + 2 * nf);
            }
        }
        __syncthreads();
        if (++stage == NSTAGE) { stage = 0; phase ^= 1; }
    }

    float inv0 = 1.f / l0, inv1 = 1.f / l1;
    int bb = bh >> 4, hh = bh & 15;
    int grow = bb * SEQ + qb * 128 + wid * 16 + (lane >> 2);
#pragma unroll
    for (int f = 0; f < 8; f++) {
        int col = hh * 64 + f * 8 + (lane & 3) * 2;
        float x0 = acc_o[f][0] * inv0, y0 = acc_o[f][1] * inv0;
        float x1 = acc_o[f][2] * inv1, y1 = acc_o[f][3] * inv1;
        size_t po0 = packed_off(grow, col, DIM);
        size_t po1 = packed_off(grow + 8, col, DIM);
        *reinterpret_cast<uint32_t*>(O0 + po0) = hpack_hi(x0, y0);
        *reinterpret_cast<uint32_t*>(O0 + po1) = hpack_hi(x1, y1);
    }
}

// ------------------------- reductions -------------------------
__device__ __forceinline__ float warp_sum(float v) {
#pragma unroll
    for (int o = 16; o; o >>= 1) v += __shfl_xor_sync(0xffffffffu, v, o);
    return v;
}

// ------------------------- layernorm -> packed fp16 -------------------------
__global__ __launch_bounds__(256) void ln_split_kernel(
    const float* __restrict__ X, const float* __restrict__ G,
    const float* __restrict__ B, char* __restrict__ Y0)
{
    __shared__ float red[8];
    int row = blockIdx.x;
    int tid = threadIdx.x;
    int lane = tid & 31, wid = tid >> 5;

    float4 v = reinterpret_cast<const float4*>(X + (size_t)row * DIM)[tid];
    float s = v.x + v.y + v.z + v.w;
    s = warp_sum(s);
    if (lane == 0) red[wid] = s;
    __syncthreads();
    if (wid == 0) {
        float t = (lane < 8) ? red[lane] : 0.f;
        t = warp_sum(t);
        if (lane == 0) red[0] = t;
    }
    __syncthreads();
    float mu = red[0] * (1.0f / DIM);
    __syncthreads();

    float4 d;
    d.x = v.x - mu; d.y = v.y - mu; d.z = v.z - mu; d.w = v.w - mu;
    float sq = d.x*d.x + d.y*d.y + d.z*d.z + d.w*d.w;
    sq = warp_sum(sq);
    if (lane == 0) red[wid] = sq;
    __syncthreads();
    if (wid == 0) {
        float t = (lane < 8) ? red[lane] : 0.f;
        t = warp_sum(t);
        if (lane == 0) red[0] = t;
    }
    __syncthreads();
    float rs = rsqrtf(red[0] * (1.0f / DIM) + 1e-5f);

    float4 g4 = reinterpret_cast<const float4*>(G)[tid];
    float4 b4 = reinterpret_cast<const float4*>(B)[tid];
    float y[4];
    y[0] = d.x * rs * g4.x + b4.x;
    y[1] = d.y * rs * g4.y + b4.y;
    y[2] = d.z * rs * g4.z + b4.z;
    y[3] = d.w * rs * g4.w + b4.w;

    size_t po = packed_off(row, tid * 4, DIM);
    *reinterpret_cast<uint2*>(Y0 + po) = make_uint2(hpack_hi(y[0], y[1]), hpack_hi(y[2], y[3]));
}

// ------------------------- weight transpose -> plain fp16 packed ----------------------
__global__ __launch_bounds__(256) void wsplit_dual(
    const float* __restrict__ Wa, char* __restrict__ Ta, int Ka, int Na,
    const float* __restrict__ Wb, char* __restrict__ Tb, int Kb, int Nb)
{
    const float* W; char* T; int K, N, n0, k0;
    if (blockIdx.z == 0) {
        W = Wa; T = Ta; K = Ka; N = Na;
        n0 = blockIdx.x * 32; k0 = blockIdx.y * 32;
    } else {
        W = Wb; T = Tb; K = Kb; N = Nb;
        n0 = blockIdx.y * 32; k0 = blockIdx.x * 32;
    }
    if (n0 >= N || k0 >= K) return;

    __shared__ float t[32][33];
    int c = threadIdx.x & 31, r = threadIdx.x >> 5;
#pragma unroll
    for (int rr = 0; rr < 32; rr += 8)
        t[r + rr][c] = W[(size_t)(k0 + r + rr) * N + n0 + c];
    __syncthreads();
    int tx = threadIdx.x & 7;
    int ty = threadIdx.x >> 3;
    int n = n0 + ty, k = k0 + tx * 4;
    float v0 = t[tx*4+0][ty], v1 = t[tx*4+1][ty], v2 = t[tx*4+2][ty], v3 = t[tx*4+3][ty];
    size_t po = packed_off(n, k, K);
    *reinterpret_cast<uint2*>(T + po) = make_uint2(hpack_hi(v0, v1), hpack_hi(v2, v3));
}

// ------------------------- launch -------------------------
extern "C" void kernel_launch(void* const* d_in, const int* in_sizes, int n_in,
                              void* d_out, int out_size)
{
    const float* x     = (const float*)d_in[0];
    const float* ln1_g = (const float*)d_in[1];
    const float* ln1_b = (const float*)d_in[2];
    const float* w_qkv = (const float*)d_in[3];
    const float* w_o   = (const float*)d_in[4];
    const float* b_o   = (const float*)d_in[5];
    const float* ln2_g = (const float*)d_in[6];
    const float* ln2_b = (const float*)d_in[7];
    const float* w1    = (const float*)d_in[8];
    const float* b1    = (const float*)d_in[9];
    const float* w2    = (const float*)d_in[10];
    const float* b2    = (const float*)d_in[11];

    float *gx;
    char *a0, *h0, *q0, *k0, *v0;
    char *wq0, *wo0, *w10, *w20;
    cudaGetSymbolAddress((void**)&gx,  g_x);
    cudaGetSymbolAddress((void**)&a0,  g_a0);
    cudaGetSymbolAddress((void**)&h0,  g_h0);
    cudaGetSymbolAddress((void**)&q0,  g_q0);
    cudaGetSymbolAddress((void**)&k0,  g_k0);
    cudaGetSymbolAddress((void**)&v0,  g_v0);
    cudaGetSymbolAddress((void**)&wq0, g_wq0);
    cudaGetSymbolAddress((void**)&wo0, g_wo0);
    cudaGetSymbolAddress((void**)&w10, g_w10);
    cudaGetSymbolAddress((void**)&w20, g_w20);

    cudaFuncSetAttribute(gemm_tc, cudaFuncAttributeMaxDynamicSharedMemorySize, SM_TOTAL);
    cudaFuncSetAttribute(flash_kernel, cudaFuncAttributeMaxDynamicSharedMemorySize, FL_TOTAL);

    wsplit_dual<<<dim3(96, 32, 2), 256>>>(w_qkv, wq0, DIM, 3 * DIM,
                                          w_o, wo0, DIM, DIM);
    wsplit_dual<<<dim3(128, 32, 2), 256>>>(w1, w10, DIM, MLPD,
                                           w2, w20, MLPD, DIM);

    for (int layer = 0; layer < 4; layer++) {
        const float* xin = (layer == 0) ? x : gx;

        // --- attention ---
        ln_split_kernel<<<RTOK, 256>>>(xin, ln1_g, ln1_b, a0);
        gemm_tc<<<dim3(3 * DIM / 128, RTOK / 128), 256, SM_TOTAL>>>(
            a0, wq0, nullptr, nullptr, nullptr, q0,
            k0, v0, 3 * DIM, DIM, 3);
        flash_kernel<<<dim3(8, NBH), 256, FL_TOTAL>>>(
            q0, k0, v0, a0);
        gemm_tc<<<dim3(DIM / 128, RTOK / 128), 256, SM_TOTAL>>>(
            a0, wo0, b_o, xin, gx, nullptr,
            nullptr, nullptr, DIM, DIM, 1);

        // --- MLP ---
        ln_split_kernel<<<RTOK, 256>>>(gx, ln2_g, ln2_b, a0);
        gemm_tc<<<dim3(MLPD / 128, RTOK / 128), 256, SM_TOTAL>>>(
            a0, w10, b1, nullptr, nullptr, h0,
            nullptr, nullptr, MLPD, DIM, 2);
        float* outp = (layer == 3) ? (float*)d_out : gx;
        gemm_tc<<<dim3(DIM / 128, RTOK / 128), 256, SM_TOTAL>>>(
            h0, w20, b2, gx, outp, nullptr,
            nullptr, nullptr, DIM, MLPD, 1);
    }
}